// round 2
// baseline (speedup 1.0000x reference)
#include <cuda_runtime.h>
#include <math.h>

#define BNN 2048
#define HSZ 256
#define ESZ 16384
#define BSZ 8
#define NSZ 256
#define NHSZ 8
#define HDSZ 32
#define VDSZ 8

// ---------------- scratch (device globals; no allocation allowed) -------------
__device__ float g_xn[BNN*HSZ];
__device__ float g_q[BNN*HSZ];
__device__ float g_k[BNN*HSZ];
__device__ float g_vv[BNN*HSZ];
__device__ float g_attn[BSZ*NHSZ*NSZ*NSZ];
__device__ float g_vatt[BNN*HSZ];
__device__ float g_vao[BNN*HSZ];
__device__ float g_dv[ESZ*HSZ];
__device__ float g_vecsumVD[BNN*HSZ];
__device__ float g_vecsum[BNN*HSZ];
__device__ float g_vec3[BNN*VDSZ*HSZ];
__device__ float g_vj[ESZ*HSZ];
__device__ float g_s12[ESZ*2*HSZ];
__device__ float g_xagg[BNN*HSZ];
__device__ float g_o[BNN*3*HSZ];
__device__ float g_fw[ESZ*HSZ];
__device__ float g_vt[BNN*VDSZ*HSZ];
__device__ float g_vs[BNN*VDSZ*HSZ];
__device__ float g_cut[ESZ];

__device__ __forceinline__ float silu_f(float x) { return x / (1.0f + __expf(-x)); }

// ---------------- LayerNorm ---------------------------------------------------
__global__ void ln_kernel(const float* __restrict__ x,
                          const float* __restrict__ w,
                          const float* __restrict__ b) {
    int n = blockIdx.x;
    int t = threadIdx.x;                 // 256 threads, one per feature
    float v = x[n*HSZ + t];
    __shared__ float red[256];
    red[t] = v; __syncthreads();
    for (int s = 128; s > 0; s >>= 1) { if (t < s) red[t] += red[t+s]; __syncthreads(); }
    float mu = red[0] * (1.0f/HSZ);
    __syncthreads();
    float d = v - mu;
    red[t] = d*d; __syncthreads();
    for (int s = 128; s > 0; s >>= 1) { if (t < s) red[t] += red[t+s]; __syncthreads(); }
    float var = red[0] * (1.0f/HSZ);
    g_xn[n*HSZ + t] = d * rsqrtf(var + 1e-5f) * w[t] + b[t];
}

// ---------------- Generic SGEMM: C = act(A@B + bias) --------------------------
// A: M x K (lda), B: K x N row-major (ldb, possibly sliced via pointer offset),
// C: M x N (ldc). grid = (N/64, M/64), block = 256. All dims divisible.
__global__ void sgemm_kernel(const float* __restrict__ A, int lda,
                             const float* __restrict__ Bm, int ldb,
                             float* __restrict__ C, int ldc,
                             const float* __restrict__ bias,
                             int K, int act) {
    __shared__ float As[16][68];
    __shared__ float Bs[16][68];
    int tid = threadIdx.x;
    int tx = tid & 15, ty = tid >> 4;
    int rowBase = blockIdx.y * 64, colBase = blockIdx.x * 64;
    const float* Ab = A + rowBase * lda;
    const float* Bb = Bm + colBase;
    float acc[4][4] = {};
    int lr = tid >> 4, lc = tid & 15;       // A-load mapping
    int br = tid >> 6, bc = tid & 63;       // B-load mapping
    for (int k0 = 0; k0 < K; k0 += 16) {
        #pragma unroll
        for (int i = 0; i < 4; i++)
            As[lc][lr + 16*i] = Ab[(lr + 16*i)*lda + k0 + lc];
        #pragma unroll
        for (int i = 0; i < 4; i++)
            Bs[br + 4*i][bc] = Bb[(k0 + br + 4*i)*ldb + bc];
        __syncthreads();
        #pragma unroll
        for (int k = 0; k < 16; k++) {
            float4 a4 = *(const float4*)&As[k][ty*4];
            float4 b4 = *(const float4*)&Bs[k][tx*4];
            float av[4] = {a4.x, a4.y, a4.z, a4.w};
            float bv[4] = {b4.x, b4.y, b4.z, b4.w};
            #pragma unroll
            for (int i = 0; i < 4; i++)
                #pragma unroll
                for (int j = 0; j < 4; j++)
                    acc[i][j] += av[i]*bv[j];
        }
        __syncthreads();
    }
    #pragma unroll
    for (int i = 0; i < 4; i++) {
        int r = rowBase + ty*4 + i;
        #pragma unroll
        for (int j = 0; j < 4; j++) {
            int c = colBase + tx*4 + j;
            float v = acc[i][j];
            if (bias) v += bias[c];
            if (act)  v = silu_f(v);
            C[r*ldc + c] = v;
        }
    }
}

// ---------------- Attention: S = silu(QK^T / sqrt(HD)) ------------------------
__global__ void attn_score_kernel() {
    // grid (NSZ/16, NSZ/16, BSZ*NHSZ), block (16,16)
    int bh = blockIdx.z;
    int b = bh / NHSZ, h = bh % NHSZ;
    int i0 = blockIdx.y * 16, j0 = blockIdx.x * 16;
    __shared__ float Qs[16][HDSZ+1], Ks[16][HDSZ+1];
    int tx = threadIdx.x, ty = threadIdx.y;
    int tid = ty*16 + tx;
    for (int i = tid; i < 16*HDSZ; i += 256) {
        int r = i >> 5, c = i & 31;
        Qs[r][c] = g_q[(b*NSZ + i0 + r)*HSZ + h*HDSZ + c];
        Ks[r][c] = g_k[(b*NSZ + j0 + r)*HSZ + h*HDSZ + c];
    }
    __syncthreads();
    float s = 0.0f;
    #pragma unroll
    for (int d = 0; d < HDSZ; d++) s += Qs[ty][d] * Ks[tx][d];
    s *= 0.1767766952966369f;   // 1/sqrt(32)
    g_attn[(bh*NSZ + i0 + ty)*NSZ + j0 + tx] = silu_f(s);
}

// vatt = (A @ Vh) / N, one thread per (b,i,h,d)
__global__ void attn_av_kernel() {
    int idx = blockIdx.x*256 + threadIdx.x;   // BNN*HSZ total
    int d = idx & 31;
    int h = (idx >> 5) & 7;
    int i = (idx >> 8) & 255;
    int b = idx >> 16;
    const float* Arow = &g_attn[((b*NHSZ + h)*NSZ + i)*NSZ];
    const float* Vb   = &g_vv[b*NSZ*HSZ + h*HDSZ + d];
    float acc = 0.0f;
    #pragma unroll 4
    for (int j = 0; j < NSZ; j++) acc += Arow[j] * Vb[j*HSZ];
    g_vatt[idx] = acc * (1.0f/NSZ);
}

// ---------------- edge-wise kernels ------------------------------------------
__global__ void cut_kernel(const float* __restrict__ r_ij) {
    int e = blockIdx.x*256 + threadIdx.x;
    if (e < ESZ) {
        float r = r_ij[e];
        float c = 0.5f * (cosf(3.14159265358979323846f * r / 5.0f) + 1.0f);
        g_cut[e] = (r < 5.0f) ? c : 0.0f;
    }
}

__global__ void vj_kernel(const int* __restrict__ ei) {
    int idx = blockIdx.x*256 + threadIdx.x;   // ESZ*HSZ
    int e = idx >> 8;
    int h = idx & 255;
    int s = ei[e];
    g_vj[idx] = g_vao[s*HSZ + h] * g_cut[e] * g_dv[idx];
}

__global__ void scatter_kernel(const int* __restrict__ ei,
                               const float* __restrict__ vecin,
                               const float* __restrict__ dij,
                               float* __restrict__ dvec_out) {
    int e = blockIdx.x;
    int h = threadIdx.x;
    int s = ei[e];
    int t = ei[ESZ + e];
    float s1 = g_s12[e*512 + h];
    float s2 = g_s12[e*512 + 256 + h];
    atomicAdd(&g_xagg[t*HSZ + h], g_vj[e*HSZ + h]);
    #pragma unroll
    for (int d = 0; d < VDSZ; d++) {
        float val = vecin[(s*VDSZ + d)*HSZ + h] * s1 + s2 * dij[e*VDSZ + d];
        atomicAdd(&dvec_out[(t*VDSZ + d)*HSZ + h], val);
    }
}

__global__ void vecsum_kernel(const float* __restrict__ vecin) {
    int idx = blockIdx.x*256 + threadIdx.x;   // BNN*HSZ
    int n = idx >> 8, h = idx & 255;
    float a = 0.0f;
    #pragma unroll
    for (int d = 0; d < VDSZ; d++) a += vecin[(n*VDSZ + d)*HSZ + h];
    g_vecsumVD[idx] = a;
}

__global__ void zero_kernel(float* __restrict__ p, int n) {
    int i = blockIdx.x*256 + threadIdx.x;
    if (i < n) p[i] = 0.0f;
}

__global__ void dx_kernel(float* __restrict__ out_dx) {
    int idx = blockIdx.x*256 + threadIdx.x;   // BNN*HSZ
    int n = idx >> 8, h = idx & 255;
    out_dx[idx] = g_vecsum[idx] * g_o[n*768 + 256 + h] + g_o[n*768 + 512 + h];
}

__global__ void dvec_final_kernel(float* __restrict__ dvec_out) {
    int idx = blockIdx.x*256 + threadIdx.x;   // BNN*VDSZ*HSZ
    int n = idx >> 11;                        // /(VD*H)=2048
    int h = idx & 255;
    dvec_out[idx] += g_vec3[idx] * g_o[n*768 + h];
}

// w_dot via expansion: sum(ab) - p1*p2*(2 - s), s = sum(d^2)
__global__ void wdot_kernel(const int* __restrict__ ei,
                            const float* __restrict__ dij,
                            float* __restrict__ df_out) {
    int e = blockIdx.x;
    int h = threadIdx.x;
    int s = ei[e];
    int t = ei[ESZ + e];
    float p1 = 0.0f, p2 = 0.0f, ab = 0.0f, s2n = 0.0f;
    #pragma unroll
    for (int d = 0; d < VDSZ; d++) {
        float dd = dij[e*VDSZ + d];
        float a = g_vt[(t*VDSZ + d)*HSZ + h];
        float b = g_vs[(s*VDSZ + d)*HSZ + h];
        ab  += a*b;
        p1  += a*dd;
        p2  += b*dd;
        s2n += dd*dd;
    }
    float wdot = ab - p1*p2*(2.0f - s2n);
    df_out[e*HSZ + h] = g_fw[e*HSZ + h] * wdot;
}

// ---------------- host launcher ----------------------------------------------
extern "C" void kernel_launch(void* const* d_in, const int* in_sizes, int n_in,
                              void* d_out, int out_size) {
    const float* x    = (const float*)d_in[0];
    const float* vec  = (const float*)d_in[1];
    const int*   ei   = (const int*)  d_in[2];
    const float* r_ij = (const float*)d_in[3];
    const float* f_ij = (const float*)d_in[4];
    const float* d_ij = (const float*)d_in[5];
    const float* ln_w = (const float*)d_in[7];
    const float* ln_b = (const float*)d_in[8];
    const float* Wq   = (const float*)d_in[9];
    const float* Wk   = (const float*)d_in[10];
    const float* Wv   = (const float*)d_in[11];
    const float* Wao  = (const float*)d_in[12];
    const float* Wvec = (const float*)d_in[13];
    const float* Wdv  = (const float*)d_in[14];
    const float* bdv  = (const float*)d_in[15];
    const float* Ws   = (const float*)d_in[16];
    const float* bs   = (const float*)d_in[17];
    const float* Wo   = (const float*)d_in[18];
    const float* bo   = (const float*)d_in[19];
    const float* Wf   = (const float*)d_in[20];
    const float* bf   = (const float*)d_in[21];
    const float* Wsrc = (const float*)d_in[22];
    const float* Wtrg = (const float*)d_in[23];

    float* out      = (float*)d_out;
    float* out_dx   = out;
    float* out_dvec = out + BNN*HSZ;
    float* out_df   = out + BNN*HSZ + BNN*VDSZ*HSZ;

    float *p_xn, *p_q, *p_k, *p_vv, *p_vatt, *p_vao, *p_dv, *p_vsVD, *p_vsum,
          *p_vec3, *p_vj, *p_s12, *p_xagg, *p_o, *p_fw, *p_vt, *p_vs;
    cudaGetSymbolAddress((void**)&p_xn,   g_xn);
    cudaGetSymbolAddress((void**)&p_q,    g_q);
    cudaGetSymbolAddress((void**)&p_k,    g_k);
    cudaGetSymbolAddress((void**)&p_vv,   g_vv);
    cudaGetSymbolAddress((void**)&p_vatt, g_vatt);
    cudaGetSymbolAddress((void**)&p_vao,  g_vao);
    cudaGetSymbolAddress((void**)&p_dv,   g_dv);
    cudaGetSymbolAddress((void**)&p_vsVD, g_vecsumVD);
    cudaGetSymbolAddress((void**)&p_vsum, g_vecsum);
    cudaGetSymbolAddress((void**)&p_vec3, g_vec3);
    cudaGetSymbolAddress((void**)&p_vj,   g_vj);
    cudaGetSymbolAddress((void**)&p_s12,  g_s12);
    cudaGetSymbolAddress((void**)&p_xagg, g_xagg);
    cudaGetSymbolAddress((void**)&p_o,    g_o);
    cudaGetSymbolAddress((void**)&p_fw,   g_fw);
    cudaGetSymbolAddress((void**)&p_vt,   g_vt);
    cudaGetSymbolAddress((void**)&p_vs,   g_vs);

    // 1. LayerNorm
    ln_kernel<<<BNN, 256>>>(x, ln_w, ln_b);

    // 2. q, k, v projections  (2048 x 256 x 256)
    sgemm_kernel<<<dim3(4, 32), 256>>>(p_xn, HSZ, Wq, HSZ, p_q,  HSZ, nullptr, HSZ, 0);
    sgemm_kernel<<<dim3(4, 32), 256>>>(p_xn, HSZ, Wk, HSZ, p_k,  HSZ, nullptr, HSZ, 0);
    sgemm_kernel<<<dim3(4, 32), 256>>>(p_xn, HSZ, Wv, HSZ, p_vv, HSZ, nullptr, HSZ, 0);

    // 3. attention
    attn_score_kernel<<<dim3(16, 16, BSZ*NHSZ), dim3(16, 16)>>>();
    attn_av_kernel<<<BNN*HSZ/256, 256>>>();
    sgemm_kernel<<<dim3(4, 32), 256>>>(p_vatt, HSZ, Wao, HSZ, p_vao, HSZ, nullptr, HSZ, 0);

    // 4. dv = silu(f_ij @ Wdv + bdv)   (16384 x 256 x 256)
    sgemm_kernel<<<dim3(4, 256), 256>>>(f_ij, HSZ, Wdv, HSZ, p_dv, HSZ, bdv, HSZ, 1);

    // 5. vec_sum = (sum_d vec) @ Wvec[:, :H] ;  vec3 = vec @ Wvec[:, H:]
    vecsum_kernel<<<BNN*HSZ/256, 256>>>(vec);
    sgemm_kernel<<<dim3(4, 32),  256>>>(p_vsVD, HSZ, Wvec,       2*HSZ, p_vsum, HSZ, nullptr, HSZ, 0);
    sgemm_kernel<<<dim3(4, 256), 256>>>(vec,    HSZ, Wvec + HSZ, 2*HSZ, p_vec3, HSZ, nullptr, HSZ, 0);

    // 6. edge features
    cut_kernel<<<ESZ/256, 256>>>(r_ij);
    vj_kernel<<<ESZ*HSZ/256, 256>>>(ei);

    // 7. s12 = silu(v_j @ Ws + bs)   (16384 x 256 x 512)
    sgemm_kernel<<<dim3(8, 256), 256>>>(p_vj, HSZ, Ws, 2*HSZ, p_s12, 2*HSZ, bs, HSZ, 1);

    // 8. segment sums (atomics): x_agg, vec_agg (vec_agg accumulated in d_out)
    zero_kernel<<<(BNN*HSZ+255)/256, 256>>>(p_xagg, BNN*HSZ);
    zero_kernel<<<(BNN*VDSZ*HSZ+255)/256, 256>>>(out_dvec, BNN*VDSZ*HSZ);
    scatter_kernel<<<ESZ, 256>>>(ei, vec, d_ij, out_dvec);

    // 9. o = x_agg @ Wo + bo   (2048 x 256 x 768)
    sgemm_kernel<<<dim3(12, 32), 256>>>(p_xagg, HSZ, Wo, 3*HSZ, p_o, 3*HSZ, bo, HSZ, 0);

    // 10. dx and dvec finalize
    dx_kernel<<<BNN*HSZ/256, 256>>>(out_dx);
    dvec_final_kernel<<<BNN*VDSZ*HSZ/256, 256>>>(out_dvec);

    // 11. df_ij = silu(f_ij @ Wf + bf) * w_dot
    sgemm_kernel<<<dim3(4, 256), 256>>>(f_ij, HSZ, Wf,   HSZ, p_fw, HSZ, bf, HSZ, 1);
    sgemm_kernel<<<dim3(4, 256), 256>>>(vec,  HSZ, Wtrg, HSZ, p_vt, HSZ, nullptr, HSZ, 0);
    sgemm_kernel<<<dim3(4, 256), 256>>>(vec,  HSZ, Wsrc, HSZ, p_vs, HSZ, nullptr, HSZ, 0);
    wdot_kernel<<<ESZ, 256>>>(ei, d_ij, out_df);
}

// round 5
// speedup vs baseline: 1.0955x; 1.0955x over previous
#include <cuda_runtime.h>
#include <cuda_bf16.h>
#include <cstdint>
#include <math.h>

#define BNN 2048
#define HSZ 256
#define ESZ 16384
#define BSZ 8
#define NSZ 256
#define NHSZ 8
#define HDSZ 32
#define VDSZ 8

#define KP 768                    // K' = 3*256 bf16 cols
#define KP_BYTES 1536

// ---------------- fp32 scratch ------------------------------------------------
__device__ float g_xn[BNN*HSZ];
__device__ float g_qkv[BNN*3*HSZ];
__device__ float g_attn[BSZ*NHSZ*NSZ*NSZ];
__device__ float g_vatt[BNN*HSZ];
__device__ float g_vao[BNN*HSZ];
__device__ float g_dvfw[ESZ*2*HSZ];          // [dv | fw] (both silu'd)
__device__ float g_vecsumVD[BNN*HSZ];
__device__ float g_vecsum[BNN*HSZ];
__device__ float g_v3ts[ESZ*3*HSZ];          // [vec3 | vt | vs] (rows = BNN*VD)
__device__ float g_vj[ESZ*HSZ];
__device__ float g_s12[ESZ*2*HSZ];
__device__ float g_xagg[BNN*HSZ];
__device__ float g_o[BNN*3*HSZ];
__device__ float g_cut[ESZ];
__device__ float g_b_dvfw[2*HSZ];

// ---------------- bf16 operand scratch (row-major [rows][768]) ----------------
__device__ __nv_bfloat16 opA_xn  [BNN*KP];
__device__ __nv_bfloat16 opA_vatt[BNN*KP];
__device__ __nv_bfloat16 opA_vsVD[BNN*KP];
__device__ __nv_bfloat16 opA_xagg[BNN*KP];
__device__ __nv_bfloat16 opA_fij [ESZ*KP];
__device__ __nv_bfloat16 opA_vec [ESZ*KP];
__device__ __nv_bfloat16 opA_vj  [ESZ*KP];
__device__ __nv_bfloat16 opB_qkv [768*KP];
__device__ __nv_bfloat16 opB_Wao [256*KP];
__device__ __nv_bfloat16 opB_dvfw[512*KP];
__device__ __nv_bfloat16 opB_Wv1 [256*KP];
__device__ __nv_bfloat16 opB_v3ts[768*KP];
__device__ __nv_bfloat16 opB_Ws  [512*KP];
__device__ __nv_bfloat16 opB_Wo  [768*KP];

__device__ __forceinline__ float silu_f(float x) { return x / (1.0f + __expf(-x)); }

// ---------------- operand conversion (fp32 -> bf16 hi/lo, row-major) ----------
// A segments along K': [hi | lo | hi]; B segments: [hi | hi | lo]
// => product terms: hi*hi + lo*hi + hi*lo  ~= exact fp32 product
__global__ void convA_kernel(const float* __restrict__ A, __nv_bfloat16* __restrict__ dst) {
    int kt = blockIdx.x, mt = blockIdx.y;
    bool lo = ((kt >> 2) == 1);
    int seg = kt >> 2;
    int kc = (kt & 3) * 64;
    for (int i = threadIdx.x; i < 1024; i += 256) {
        int r = i >> 3, u = i & 7;
        const float* src = A + (size_t)(mt*128 + r)*HSZ + kc + u*8;
        float4 f0 = *(const float4*)src;
        float4 f1 = *(const float4*)(src + 4);
        float f[8] = {f0.x, f0.y, f0.z, f0.w, f1.x, f1.y, f1.z, f1.w};
        union { __nv_bfloat16 h[8]; uint4 u4; } o;
        #pragma unroll
        for (int j = 0; j < 8; j++) {
            __nv_bfloat16 hi = __float2bfloat16(f[j]);
            o.h[j] = lo ? __float2bfloat16(f[j] - __bfloat162float(hi)) : hi;
        }
        *(uint4*)(dst + (size_t)(mt*128 + r)*KP + seg*256 + kc + u*8) = o.u4;
    }
}

__global__ void convB_kernel(const float* __restrict__ B, __nv_bfloat16* __restrict__ dst,
                             int ldb, int colOff) {
    int kt = blockIdx.x, nt = blockIdx.y;
    bool lo = ((kt >> 2) == 2);
    int seg = kt >> 2;
    int kc = (kt & 3) * 64;
    for (int i = threadIdx.x; i < 1024; i += 256) {
        int r = i >> 3, u = i & 7;
        int gn = nt*128 + r + colOff;
        union { __nv_bfloat16 h[8]; uint4 u4; } o;
        #pragma unroll
        for (int j = 0; j < 8; j++) {
            float v = B[(size_t)(kc + u*8 + j)*ldb + gn];
            __nv_bfloat16 hi = __float2bfloat16(v);
            o.h[j] = lo ? __float2bfloat16(v - __bfloat162float(hi)) : hi;
        }
        *(uint4*)(dst + (size_t)(nt*128 + r)*KP + seg*256 + kc + u*8) = o.u4;
    }
}

// ---------------- mma.sync bf16x3 GEMM: C = act(Aop @ Bop^T + bias) -----------
// Block 128x128, 8 warps (4x2) of 32x64, BK=32 bf16, double-buffered cp.async.
// smem pitch 80B per 32-bf16 row => conflict-free ldmatrix.
#define SPITCH 80
#define STILE (128*SPITCH)       // 10240 per operand tile
#define SSTAGE (2*STILE)         // 20480 per stage

__device__ __forceinline__ uint32_t smem_u32(const void* p) {
    uint32_t a;
    asm("{ .reg .u64 t; cvta.to.shared.u64 t, %1; cvt.u32.u64 %0, t; }" : "=r"(a) : "l"(p));
    return a;
}

__global__ void __launch_bounds__(256) gemm_mma(
    const __nv_bfloat16* __restrict__ Aop, const __nv_bfloat16* __restrict__ Bop,
    float* __restrict__ C, int ldc, const float* __restrict__ bias, int act)
{
    __shared__ __align__(16) char smem[2*SSTAGE];   // 40960 bytes
    int tid = threadIdx.x;
    int lane = tid & 31, wid = tid >> 5;
    int wm = wid & 3, wn = wid >> 2;
    int nt = blockIdx.x, mt = blockIdx.y;
    const char* gA = (const char*)Aop + (size_t)mt*128*KP_BYTES;
    const char* gB = (const char*)Bop + (size_t)nt*128*KP_BYTES;
    uint32_t sbase = smem_u32(smem);

    auto load_stage = [&](int buf, int s) {
        uint32_t dst0 = sbase + buf*SSTAGE;
        #pragma unroll
        for (int t = 0; t < 4; t++) {
            int ci = tid + t*256;          // 1024 chunks of 16B (512 A + 512 B)
            int isB = ci >> 9;
            int cc = ci & 511;
            int row = cc >> 2, c = cc & 3;
            uint32_t dst = dst0 + isB*STILE + row*SPITCH + c*16;
            const char* src = (isB ? gB : gA) + (size_t)row*KP_BYTES + s*64 + c*16;
            asm volatile("cp.async.cg.shared.global [%0], [%1], 16;\n" :: "r"(dst), "l"(src));
        }
        asm volatile("cp.async.commit_group;\n");
    };

    float acc[2][8][4];
    #pragma unroll
    for (int i = 0; i < 2; i++)
        #pragma unroll
        for (int j = 0; j < 8; j++)
            #pragma unroll
            for (int k = 0; k < 4; k++) acc[i][j][k] = 0.0f;

    load_stage(0, 0);
    const int NS = KP/32;   // 24
    for (int s = 0; s < NS; s++) {
        int buf = s & 1;
        if (s + 1 < NS) {
            load_stage(buf ^ 1, s + 1);
            asm volatile("cp.async.wait_group 1;\n");
        } else {
            asm volatile("cp.async.wait_group 0;\n");
        }
        __syncthreads();
        uint32_t bA = sbase + buf*SSTAGE;
        uint32_t bB = bA + STILE;
        #pragma unroll
        for (int kk = 0; kk < 32; kk += 16) {
            uint32_t a[2][4];
            #pragma unroll
            for (int mb = 0; mb < 2; mb++) {
                uint32_t addr = bA + (wm*32 + mb*16 + (lane & 15))*SPITCH
                                   + (kk + ((lane >> 4) << 3))*2;
                asm volatile("ldmatrix.sync.aligned.m8n8.x4.shared.b16 {%0,%1,%2,%3}, [%4];"
                    : "=r"(a[mb][0]), "=r"(a[mb][1]), "=r"(a[mb][2]), "=r"(a[mb][3]) : "r"(addr));
            }
            uint32_t b[8][2];
            #pragma unroll
            for (int nb4 = 0; nb4 < 4; nb4++) {
                uint32_t r0, r1, r2, r3;
                uint32_t addr = bB + (wn*64 + nb4*16 + (lane & 15))*SPITCH
                                   + (kk + ((lane >> 4) << 3))*2;
                asm volatile("ldmatrix.sync.aligned.m8n8.x4.shared.b16 {%0,%1,%2,%3}, [%4];"
                    : "=r"(r0), "=r"(r1), "=r"(r2), "=r"(r3) : "r"(addr));
                b[nb4*2][0] = r0; b[nb4*2][1] = r2;
                b[nb4*2+1][0] = r1; b[nb4*2+1][1] = r3;
            }
            #pragma unroll
            for (int mb = 0; mb < 2; mb++)
                #pragma unroll
                for (int nb = 0; nb < 8; nb++)
                    asm volatile("mma.sync.aligned.m16n8k16.row.col.f32.bf16.bf16.f32 "
                        "{%0,%1,%2,%3}, {%4,%5,%6,%7}, {%8,%9}, {%0,%1,%2,%3};"
                        : "+f"(acc[mb][nb][0]), "+f"(acc[mb][nb][1]),
                          "+f"(acc[mb][nb][2]), "+f"(acc[mb][nb][3])
                        : "r"(a[mb][0]), "r"(a[mb][1]), "r"(a[mb][2]), "r"(a[mb][3]),
                          "r"(b[nb][0]), "r"(b[nb][1]));
        }
        __syncthreads();
    }

    int rbase = mt*128 + wm*32 + (lane >> 2);
    int cbase = nt*128 + wn*64 + (lane & 3)*2;
    #pragma unroll
    for (int mb = 0; mb < 2; mb++) {
        #pragma unroll
        for (int nb = 0; nb < 8; nb++) {
            int col = cbase + nb*8;
            float bv0 = 0.0f, bv1 = 0.0f;
            if (bias) { bv0 = bias[col]; bv1 = bias[col+1]; }
            float v0 = acc[mb][nb][0] + bv0, v1 = acc[mb][nb][1] + bv1;
            float v2 = acc[mb][nb][2] + bv0, v3 = acc[mb][nb][3] + bv1;
            if (act) { v0 = silu_f(v0); v1 = silu_f(v1); v2 = silu_f(v2); v3 = silu_f(v3); }
            int r0 = rbase + mb*16;
            *(float2*)&C[(size_t)r0*ldc + col]     = make_float2(v0, v1);
            *(float2*)&C[(size_t)(r0+8)*ldc + col] = make_float2(v2, v3);
        }
    }
}

// ---------------- LayerNorm ---------------------------------------------------
__global__ void ln_kernel(const float* __restrict__ x,
                          const float* __restrict__ w,
                          const float* __restrict__ b) {
    int n = blockIdx.x;
    int t = threadIdx.x;
    float v = x[n*HSZ + t];
    __shared__ float red[256];
    red[t] = v; __syncthreads();
    for (int s = 128; s > 0; s >>= 1) { if (t < s) red[t] += red[t+s]; __syncthreads(); }
    float mu = red[0] * (1.0f/HSZ);
    __syncthreads();
    float d = v - mu;
    red[t] = d*d; __syncthreads();
    for (int s = 128; s > 0; s >>= 1) { if (t < s) red[t] += red[t+s]; __syncthreads(); }
    float var = red[0] * (1.0f/HSZ);
    g_xn[n*HSZ + t] = d * rsqrtf(var + 1e-5f) * w[t] + b[t];
}

// ---------------- attention ---------------------------------------------------
__global__ void attn_score_kernel() {
    int bh = blockIdx.z;
    int b = bh / NHSZ, h = bh % NHSZ;
    int i0 = blockIdx.y * 16, j0 = blockIdx.x * 16;
    __shared__ float Qs[16][HDSZ+1], Ks[16][HDSZ+1];
    int tx = threadIdx.x, ty = threadIdx.y;
    int tid = ty*16 + tx;
    for (int i = tid; i < 16*HDSZ; i += 256) {
        int r = i >> 5, c = i & 31;
        Qs[r][c] = g_qkv[(size_t)(b*NSZ + i0 + r)*768 + h*HDSZ + c];
        Ks[r][c] = g_qkv[(size_t)(b*NSZ + j0 + r)*768 + 256 + h*HDSZ + c];
    }
    __syncthreads();
    float s = 0.0f;
    #pragma unroll
    for (int d = 0; d < HDSZ; d++) s += Qs[ty][d] * Ks[tx][d];
    s *= 0.1767766952966369f;
    g_attn[((size_t)bh*NSZ + i0 + ty)*NSZ + j0 + tx] = silu_f(s);
}

__global__ void attn_av_kernel() {
    int idx = blockIdx.x*256 + threadIdx.x;
    int d = idx & 31;
    int h = (idx >> 5) & 7;
    int i = (idx >> 8) & 255;
    int b = idx >> 16;
    const float* Arow = &g_attn[(((size_t)b*NHSZ + h)*NSZ + i)*NSZ];
    const float* Vb   = &g_qkv[(size_t)b*NSZ*768 + 512 + h*HDSZ + d];
    float acc = 0.0f;
    #pragma unroll 4
    for (int j = 0; j < NSZ; j++) acc += Arow[j] * Vb[(size_t)j*768];
    g_vatt[idx] = acc * (1.0f/NSZ);
}

// ---------------- edge-wise / elementwise -------------------------------------
__global__ void cut_kernel(const float* __restrict__ r_ij) {
    int e = blockIdx.x*256 + threadIdx.x;
    if (e < ESZ) {
        float r = r_ij[e];
        float c = 0.5f * (cosf(3.14159265358979323846f * r / 5.0f) + 1.0f);
        g_cut[e] = (r < 5.0f) ? c : 0.0f;
    }
}

__global__ void concat_bias_kernel(const float* __restrict__ a, const float* __restrict__ b) {
    int i = blockIdx.x*256 + threadIdx.x;
    if (i < 256) g_b_dvfw[i] = a[i];
    else if (i < 512) g_b_dvfw[i] = b[i - 256];
}

__global__ void vj_kernel(const int* __restrict__ ei) {
    int idx = blockIdx.x*256 + threadIdx.x;
    int e = idx >> 8;
    int h = idx & 255;
    int s = ei[e];
    g_vj[idx] = g_vao[s*HSZ + h] * g_cut[e] * g_dvfw[(size_t)e*512 + h];
}

__global__ void scatter_kernel(const int* __restrict__ ei,
                               const float* __restrict__ vecin,
                               const float* __restrict__ dij,
                               float* __restrict__ dvec_out) {
    int e = blockIdx.x;
    int h = threadIdx.x;
    int s = ei[e];
    int t = ei[ESZ + e];
    float s1 = g_s12[(size_t)e*512 + h];
    float s2 = g_s12[(size_t)e*512 + 256 + h];
    atomicAdd(&g_xagg[t*HSZ + h], g_vj[e*HSZ + h]);
    #pragma unroll
    for (int d = 0; d < VDSZ; d++) {
        float val = vecin[(size_t)(s*VDSZ + d)*HSZ + h] * s1 + s2 * dij[e*VDSZ + d];
        atomicAdd(&dvec_out[(size_t)(t*VDSZ + d)*HSZ + h], val);
    }
}

__global__ void vecsum_kernel(const float* __restrict__ vecin) {
    int idx = blockIdx.x*256 + threadIdx.x;
    int n = idx >> 8, h = idx & 255;
    float a = 0.0f;
    #pragma unroll
    for (int d = 0; d < VDSZ; d++) a += vecin[(size_t)(n*VDSZ + d)*HSZ + h];
    g_vecsumVD[idx] = a;
}

__global__ void zero_kernel(float* __restrict__ p, int n) {
    int i = blockIdx.x*256 + threadIdx.x;
    if (i < n) p[i] = 0.0f;
}

__global__ void dx_kernel(float* __restrict__ out_dx) {
    int idx = blockIdx.x*256 + threadIdx.x;
    int n = idx >> 8, h = idx & 255;
    out_dx[idx] = g_vecsum[idx] * g_o[(size_t)n*768 + 256 + h] + g_o[(size_t)n*768 + 512 + h];
}

__global__ void dvec_final_kernel(float* __restrict__ dvec_out) {
    int idx = blockIdx.x*256 + threadIdx.x;     // BNN*VD*H
    int n = idx >> 11;
    int d = (idx >> 8) & 7;
    int h = idx & 255;
    dvec_out[idx] += g_v3ts[(size_t)(n*VDSZ + d)*768 + h] * g_o[(size_t)n*768 + h];
}

__global__ void wdot_kernel(const int* __restrict__ ei,
                            const float* __restrict__ dij,
                            float* __restrict__ df_out) {
    int e = blockIdx.x;
    int h = threadIdx.x;
    int s = ei[e];
    int t = ei[ESZ + e];
    float p1 = 0.0f, p2 = 0.0f, ab = 0.0f, s2n = 0.0f;
    #pragma unroll
    for (int d = 0; d < VDSZ; d++) {
        float dd = dij[e*VDSZ + d];
        float a = g_v3ts[(size_t)(t*VDSZ + d)*768 + 256 + h];
        float b = g_v3ts[(size_t)(s*VDSZ + d)*768 + 512 + h];
        ab  += a*b;
        p1  += a*dd;
        p2  += b*dd;
        s2n += dd*dd;
    }
    float wdot = ab - p1*p2*(2.0f - s2n);
    df_out[(size_t)e*HSZ + h] = g_dvfw[(size_t)e*512 + 256 + h] * wdot;
}

// ---------------- host launcher ----------------------------------------------
extern "C" void kernel_launch(void* const* d_in, const int* in_sizes, int n_in,
                              void* d_out, int out_size) {
    const float* x    = (const float*)d_in[0];
    const float* vec  = (const float*)d_in[1];
    const int*   ei   = (const int*)  d_in[2];
    const float* r_ij = (const float*)d_in[3];
    const float* f_ij = (const float*)d_in[4];
    const float* d_ij = (const float*)d_in[5];
    const float* ln_w = (const float*)d_in[7];
    const float* ln_b = (const float*)d_in[8];
    const float* Wq   = (const float*)d_in[9];
    const float* Wk   = (const float*)d_in[10];
    const float* Wv   = (const float*)d_in[11];
    const float* Wao  = (const float*)d_in[12];
    const float* Wvec = (const float*)d_in[13];
    const float* Wdv  = (const float*)d_in[14];
    const float* bdv  = (const float*)d_in[15];
    const float* Ws   = (const float*)d_in[16];
    const float* bs   = (const float*)d_in[17];
    const float* Wo   = (const float*)d_in[18];
    const float* bo   = (const float*)d_in[19];
    const float* Wf   = (const float*)d_in[20];
    const float* bf   = (const float*)d_in[21];
    const float* Wsrc = (const float*)d_in[22];
    const float* Wtrg = (const float*)d_in[23];

    float* out      = (float*)d_out;
    float* out_dx   = out;
    float* out_dvec = out + BNN*HSZ;
    float* out_df   = out + BNN*HSZ + BNN*VDSZ*HSZ;

    float *p_xn, *p_qkv, *p_vatt, *p_vao, *p_dvfw, *p_vsVD, *p_vsum,
          *p_v3ts, *p_vj, *p_s12, *p_xagg, *p_o, *p_bdvfw;
    cudaGetSymbolAddress((void**)&p_xn,   g_xn);
    cudaGetSymbolAddress((void**)&p_qkv,  g_qkv);
    cudaGetSymbolAddress((void**)&p_vatt, g_vatt);
    cudaGetSymbolAddress((void**)&p_vao,  g_vao);
    cudaGetSymbolAddress((void**)&p_dvfw, g_dvfw);
    cudaGetSymbolAddress((void**)&p_vsVD, g_vecsumVD);
    cudaGetSymbolAddress((void**)&p_vsum, g_vecsum);
    cudaGetSymbolAddress((void**)&p_v3ts, g_v3ts);
    cudaGetSymbolAddress((void**)&p_vj,   g_vj);
    cudaGetSymbolAddress((void**)&p_s12,  g_s12);
    cudaGetSymbolAddress((void**)&p_xagg, g_xagg);
    cudaGetSymbolAddress((void**)&p_o,    g_o);
    cudaGetSymbolAddress((void**)&p_bdvfw, g_b_dvfw);

    __nv_bfloat16 *pA_xn, *pA_vatt, *pA_vsVD, *pA_xagg, *pA_fij, *pA_vec, *pA_vj;
    __nv_bfloat16 *pB_qkv, *pB_Wao, *pB_dvfw, *pB_Wv1, *pB_v3ts, *pB_Ws, *pB_Wo;
    cudaGetSymbolAddress((void**)&pA_xn,   opA_xn);
    cudaGetSymbolAddress((void**)&pA_vatt, opA_vatt);
    cudaGetSymbolAddress((void**)&pA_vsVD, opA_vsVD);
    cudaGetSymbolAddress((void**)&pA_xagg, opA_xagg);
    cudaGetSymbolAddress((void**)&pA_fij,  opA_fij);
    cudaGetSymbolAddress((void**)&pA_vec,  opA_vec);
    cudaGetSymbolAddress((void**)&pA_vj,   opA_vj);
    cudaGetSymbolAddress((void**)&pB_qkv,  opB_qkv);
    cudaGetSymbolAddress((void**)&pB_Wao,  opB_Wao);
    cudaGetSymbolAddress((void**)&pB_dvfw, opB_dvfw);
    cudaGetSymbolAddress((void**)&pB_Wv1,  opB_Wv1);
    cudaGetSymbolAddress((void**)&pB_v3ts, opB_v3ts);
    cudaGetSymbolAddress((void**)&pB_Ws,   opB_Ws);
    cudaGetSymbolAddress((void**)&pB_Wo,   opB_Wo);

    const size_t NTS = (size_t)256*KP;   // 2 n-tiles (256 cols) worth of rows

    // ---- weight conversions (independent) ----
    convB_kernel<<<dim3(12,2),256>>>(Wq,   pB_qkv,           256, 0);
    convB_kernel<<<dim3(12,2),256>>>(Wk,   pB_qkv + NTS,     256, 0);
    convB_kernel<<<dim3(12,2),256>>>(Wv,   pB_qkv + 2*NTS,   256, 0);
    convB_kernel<<<dim3(12,2),256>>>(Wao,  pB_Wao,           256, 0);
    convB_kernel<<<dim3(12,2),256>>>(Wdv,  pB_dvfw,          256, 0);
    convB_kernel<<<dim3(12,2),256>>>(Wf,   pB_dvfw + NTS,    256, 0);
    convB_kernel<<<dim3(12,2),256>>>(Wvec, pB_Wv1,           512, 0);
    convB_kernel<<<dim3(12,2),256>>>(Wvec, pB_v3ts,          512, 256);
    convB_kernel<<<dim3(12,2),256>>>(Wtrg, pB_v3ts + NTS,    256, 0);
    convB_kernel<<<dim3(12,2),256>>>(Wsrc, pB_v3ts + 2*NTS,  256, 0);
    convB_kernel<<<dim3(12,4),256>>>(Ws,   pB_Ws,            512, 0);
    convB_kernel<<<dim3(12,6),256>>>(Wo,   pB_Wo,            768, 0);
    concat_bias_kernel<<<2,256>>>(bdv, bf);

    // ---- node pipeline ----
    ln_kernel<<<BNN,256>>>(x, ln_w, ln_b);
    convA_kernel<<<dim3(12,16),256>>>(p_xn, pA_xn);
    gemm_mma<<<dim3(6,16),256>>>(pA_xn, pB_qkv, p_qkv, 768, nullptr, 0);

    attn_score_kernel<<<dim3(16,16,BSZ*NHSZ),dim3(16,16)>>>();
    attn_av_kernel<<<BNN*HSZ/256,256>>>();
    convA_kernel<<<dim3(12,16),256>>>(p_vatt, pA_vatt);
    gemm_mma<<<dim3(2,16),256>>>(pA_vatt, pB_Wao, p_vao, 256, nullptr, 0);

    // ---- edge pipeline ----
    convA_kernel<<<dim3(12,128),256>>>(f_ij, pA_fij);
    gemm_mma<<<dim3(4,128),256>>>(pA_fij, pB_dvfw, p_dvfw, 512, p_bdvfw, 1);

    vecsum_kernel<<<BNN*HSZ/256,256>>>(vec);
    convA_kernel<<<dim3(12,16),256>>>(p_vsVD, pA_vsVD);
    gemm_mma<<<dim3(2,16),256>>>(pA_vsVD, pB_Wv1, p_vsum, 256, nullptr, 0);

    convA_kernel<<<dim3(12,128),256>>>(vec, pA_vec);
    gemm_mma<<<dim3(6,128),256>>>(pA_vec, pB_v3ts, p_v3ts, 768, nullptr, 0);

    cut_kernel<<<ESZ/256,256>>>(r_ij);
    vj_kernel<<<ESZ*HSZ/256,256>>>(ei);
    convA_kernel<<<dim3(12,128),256>>>(p_vj, pA_vj);
    gemm_mma<<<dim3(4,128),256>>>(pA_vj, pB_Ws, p_s12, 512, bs, 1);

    zero_kernel<<<(BNN*HSZ+255)/256,256>>>(p_xagg, BNN*HSZ);
    zero_kernel<<<(BNN*VDSZ*HSZ+255)/256,256>>>(out_dvec, BNN*VDSZ*HSZ);
    scatter_kernel<<<ESZ,256>>>(ei, vec, d_ij, out_dvec);

    convA_kernel<<<dim3(12,16),256>>>(p_xagg, pA_xagg);
    gemm_mma<<<dim3(6,16),256>>>(pA_xagg, pB_Wo, p_o, 768, bo, 0);

    dx_kernel<<<BNN*HSZ/256,256>>>(out_dx);
    dvec_final_kernel<<<BNN*VDSZ*HSZ/256,256>>>(out_dvec);
    wdot_kernel<<<ESZ,256>>>(ei, d_ij, out_df);
}

// round 6
// speedup vs baseline: 1.5818x; 1.4439x over previous
#include <cuda_runtime.h>
#include <cuda_bf16.h>
#include <cstdint>
#include <math.h>

#define BNN 2048
#define HSZ 256
#define ESZ 16384
#define BSZ 8
#define NSZ 256
#define NHSZ 8
#define HDSZ 32
#define VDSZ 8

#define KP 768                    // K' = 3*256 bf16 cols
#define KP_BYTES 1536

// ---------------- fp32 scratch ------------------------------------------------
__device__ float g_xn[BNN*HSZ];
__device__ float g_qkv[BNN*3*HSZ];
__device__ float g_vatt[BNN*HSZ];
__device__ float g_vao[BNN*HSZ];
__device__ float g_dvfw[ESZ*2*HSZ];          // [dv | fw] (both silu'd)
__device__ float g_vecsumVD[BNN*HSZ];
__device__ float g_vecsum[BNN*HSZ];
__device__ float g_v3ts[ESZ*3*HSZ];          // [vec3 | vt | vs] (rows = BNN*VD)
__device__ float g_vj[ESZ*HSZ];
__device__ float g_s12[ESZ*2*HSZ];
__device__ float g_xagg[BNN*HSZ];
__device__ float g_o[BNN*3*HSZ];
__device__ float g_cut[ESZ];
__device__ float g_b_dvfw[2*HSZ];

// ---------------- bf16 operand scratch (row-major [rows][768]) ----------------
__device__ __nv_bfloat16 opA_xn  [BNN*KP];
__device__ __nv_bfloat16 opA_vatt[BNN*KP];
__device__ __nv_bfloat16 opA_vsVD[BNN*KP];
__device__ __nv_bfloat16 opA_xagg[BNN*KP];
__device__ __nv_bfloat16 opA_fij [ESZ*KP];
__device__ __nv_bfloat16 opA_vec [ESZ*KP];
__device__ __nv_bfloat16 opA_vj  [ESZ*KP];
__device__ __nv_bfloat16 opB_qkv [768*KP];
__device__ __nv_bfloat16 opB_Wao [256*KP];
__device__ __nv_bfloat16 opB_dvfw[512*KP];
__device__ __nv_bfloat16 opB_Wv1 [256*KP];
__device__ __nv_bfloat16 opB_v3ts[768*KP];
__device__ __nv_bfloat16 opB_Ws  [512*KP];
__device__ __nv_bfloat16 opB_Wo  [768*KP];

__device__ __forceinline__ float silu_f(float x) { return x / (1.0f + __expf(-x)); }

// ---------------- operand conversion A (fp32 -> bf16 hi/lo, row-major) --------
// A segments along K': [hi | lo | hi]; B segments: [hi | hi | lo]
__global__ void convA_kernel(const float* __restrict__ A, __nv_bfloat16* __restrict__ dst) {
    int kt = blockIdx.x, mt = blockIdx.y;
    bool lo = ((kt >> 2) == 1);
    int seg = kt >> 2;
    int kc = (kt & 3) * 64;
    for (int i = threadIdx.x; i < 1024; i += 256) {
        int r = i >> 3, u = i & 7;
        const float* src = A + (size_t)(mt*128 + r)*HSZ + kc + u*8;
        float4 f0 = *(const float4*)src;
        float4 f1 = *(const float4*)(src + 4);
        float f[8] = {f0.x, f0.y, f0.z, f0.w, f1.x, f1.y, f1.z, f1.w};
        union { __nv_bfloat16 h[8]; uint4 u4; } o;
        #pragma unroll
        for (int j = 0; j < 8; j++) {
            __nv_bfloat16 hi = __float2bfloat16(f[j]);
            o.h[j] = lo ? __float2bfloat16(f[j] - __bfloat162float(hi)) : hi;
        }
        *(uint4*)(dst + (size_t)(mt*128 + r)*KP + seg*256 + kc + u*8) = o.u4;
    }
}

// ---------------- fused weight conversion (all 12 jobs, coalesced) ------------
// Each block: one (job, n-tile 64, k-tile 64). Reads W row-major coalesced,
// transposes through smem, writes dst[gn*768 + seg*256 + k] for seg {0,1}=hi, 2=lo.
__global__ void __launch_bounds__(256) conv_weights(
    const float* __restrict__ Wq, const float* __restrict__ Wk, const float* __restrict__ Wv,
    const float* __restrict__ Wao, const float* __restrict__ Wdv, const float* __restrict__ Wf,
    const float* __restrict__ Wvec, const float* __restrict__ Wtrg, const float* __restrict__ Wsrc,
    const float* __restrict__ Ws, const float* __restrict__ Wo,
    __nv_bfloat16* __restrict__ dq, __nv_bfloat16* __restrict__ dao,
    __nv_bfloat16* __restrict__ ddvfw, __nv_bfloat16* __restrict__ dwv1,
    __nv_bfloat16* __restrict__ dv3ts, __nv_bfloat16* __restrict__ dws,
    __nv_bfloat16* __restrict__ dwo)
{
    int t = blockIdx.x;
    const float* src; __nv_bfloat16* dst; int ldb, colOff, ntn, local;
    if (t < 160) {
        int j = t >> 4; local = t & 15; ntn = 4;
        switch (j) {
            case 0: src = Wq;   dst = dq;                       ldb = 256; colOff = 0;   break;
            case 1: src = Wk;   dst = dq + (size_t)256*KP;      ldb = 256; colOff = 0;   break;
            case 2: src = Wv;   dst = dq + (size_t)512*KP;      ldb = 256; colOff = 0;   break;
            case 3: src = Wao;  dst = dao;                      ldb = 256; colOff = 0;   break;
            case 4: src = Wdv;  dst = ddvfw;                    ldb = 256; colOff = 0;   break;
            case 5: src = Wf;   dst = ddvfw + (size_t)256*KP;   ldb = 256; colOff = 0;   break;
            case 6: src = Wvec; dst = dwv1;                     ldb = 512; colOff = 0;   break;
            case 7: src = Wvec; dst = dv3ts;                    ldb = 512; colOff = 256; break;
            case 8: src = Wtrg; dst = dv3ts + (size_t)256*KP;   ldb = 256; colOff = 0;   break;
            default:src = Wsrc; dst = dv3ts + (size_t)512*KP;   ldb = 256; colOff = 0;   break;
        }
    } else if (t < 192) {
        local = t - 160; ntn = 8;
        src = Ws; dst = dws; ldb = 512; colOff = 0;
    } else {
        local = t - 192; ntn = 12;
        src = Wo; dst = dwo; ldb = 768; colOff = 0;
    }
    int nt = local % ntn;
    int kt = local / ntn;
    int base_k = kt * 64;
    int base_n = colOff + nt * 64;

    __shared__ float Wt[64][65];
    int tid = threadIdx.x;
    for (int i = tid; i < 4096; i += 256) {
        int r = i >> 6, c = i & 63;
        Wt[r][c] = src[(size_t)(base_k + r)*ldb + base_n + c];
    }
    __syncthreads();
    for (int i = tid; i < 2048; i += 256) {
        int c = i >> 5;
        int k2 = (i & 31) * 2;
        float v0 = Wt[k2][c], v1 = Wt[k2+1][c];
        __nv_bfloat16 h0 = __float2bfloat16(v0), h1 = __float2bfloat16(v1);
        __nv_bfloat16 l0 = __float2bfloat16(v0 - __bfloat162float(h0));
        __nv_bfloat16 l1 = __float2bfloat16(v1 - __bfloat162float(h1));
        union { __nv_bfloat16 h[2]; uint32_t u; } hp, lp;
        hp.h[0] = h0; hp.h[1] = h1; lp.h[0] = l0; lp.h[1] = l1;
        size_t ro = (size_t)(nt*64 + c)*KP + kt*64 + k2;
        *(uint32_t*)&dst[ro]       = hp.u;   // seg0 hi
        *(uint32_t*)&dst[ro + 256] = hp.u;   // seg1 hi
        *(uint32_t*)&dst[ro + 512] = lp.u;   // seg2 lo
    }
}

// ---------------- mma.sync bf16x3 GEMM (unchanged from passing R5) ------------
#define SPITCH 80
#define STILE (128*SPITCH)
#define SSTAGE (2*STILE)

__device__ __forceinline__ uint32_t smem_u32(const void* p) {
    uint32_t a;
    asm("{ .reg .u64 t; cvta.to.shared.u64 t, %1; cvt.u32.u64 %0, t; }" : "=r"(a) : "l"(p));
    return a;
}

__global__ void __launch_bounds__(256) gemm_mma(
    const __nv_bfloat16* __restrict__ Aop, const __nv_bfloat16* __restrict__ Bop,
    float* __restrict__ C, int ldc, const float* __restrict__ bias, int act)
{
    __shared__ __align__(16) char smem[2*SSTAGE];
    int tid = threadIdx.x;
    int lane = tid & 31, wid = tid >> 5;
    int wm = wid & 3, wn = wid >> 2;
    int nt = blockIdx.x, mt = blockIdx.y;
    const char* gA = (const char*)Aop + (size_t)mt*128*KP_BYTES;
    const char* gB = (const char*)Bop + (size_t)nt*128*KP_BYTES;
    uint32_t sbase = smem_u32(smem);

    auto load_stage = [&](int buf, int s) {
        uint32_t dst0 = sbase + buf*SSTAGE;
        #pragma unroll
        for (int t = 0; t < 4; t++) {
            int ci = tid + t*256;
            int isB = ci >> 9;
            int cc = ci & 511;
            int row = cc >> 2, c = cc & 3;
            uint32_t dst = dst0 + isB*STILE + row*SPITCH + c*16;
            const char* src = (isB ? gB : gA) + (size_t)row*KP_BYTES + s*64 + c*16;
            asm volatile("cp.async.cg.shared.global [%0], [%1], 16;\n" :: "r"(dst), "l"(src));
        }
        asm volatile("cp.async.commit_group;\n");
    };

    float acc[2][8][4];
    #pragma unroll
    for (int i = 0; i < 2; i++)
        #pragma unroll
        for (int j = 0; j < 8; j++)
            #pragma unroll
            for (int k = 0; k < 4; k++) acc[i][j][k] = 0.0f;

    load_stage(0, 0);
    const int NS = KP/32;
    for (int s = 0; s < NS; s++) {
        int buf = s & 1;
        if (s + 1 < NS) {
            load_stage(buf ^ 1, s + 1);
            asm volatile("cp.async.wait_group 1;\n");
        } else {
            asm volatile("cp.async.wait_group 0;\n");
        }
        __syncthreads();
        uint32_t bA = sbase + buf*SSTAGE;
        uint32_t bB = bA + STILE;
        #pragma unroll
        for (int kk = 0; kk < 32; kk += 16) {
            uint32_t a[2][4];
            #pragma unroll
            for (int mb = 0; mb < 2; mb++) {
                uint32_t addr = bA + (wm*32 + mb*16 + (lane & 15))*SPITCH
                                   + (kk + ((lane >> 4) << 3))*2;
                asm volatile("ldmatrix.sync.aligned.m8n8.x4.shared.b16 {%0,%1,%2,%3}, [%4];"
                    : "=r"(a[mb][0]), "=r"(a[mb][1]), "=r"(a[mb][2]), "=r"(a[mb][3]) : "r"(addr));
            }
            uint32_t b[8][2];
            #pragma unroll
            for (int nb4 = 0; nb4 < 4; nb4++) {
                uint32_t r0, r1, r2, r3;
                uint32_t addr = bB + (wn*64 + nb4*16 + (lane & 15))*SPITCH
                                   + (kk + ((lane >> 4) << 3))*2;
                asm volatile("ldmatrix.sync.aligned.m8n8.x4.shared.b16 {%0,%1,%2,%3}, [%4];"
                    : "=r"(r0), "=r"(r1), "=r"(r2), "=r"(r3) : "r"(addr));
                b[nb4*2][0] = r0; b[nb4*2][1] = r2;
                b[nb4*2+1][0] = r1; b[nb4*2+1][1] = r3;
            }
            #pragma unroll
            for (int mb = 0; mb < 2; mb++)
                #pragma unroll
                for (int nb = 0; nb < 8; nb++)
                    asm volatile("mma.sync.aligned.m16n8k16.row.col.f32.bf16.bf16.f32 "
                        "{%0,%1,%2,%3}, {%4,%5,%6,%7}, {%8,%9}, {%0,%1,%2,%3};"
                        : "+f"(acc[mb][nb][0]), "+f"(acc[mb][nb][1]),
                          "+f"(acc[mb][nb][2]), "+f"(acc[mb][nb][3])
                        : "r"(a[mb][0]), "r"(a[mb][1]), "r"(a[mb][2]), "r"(a[mb][3]),
                          "r"(b[nb][0]), "r"(b[nb][1]));
        }
        __syncthreads();
    }

    int rbase = mt*128 + wm*32 + (lane >> 2);
    int cbase = nt*128 + wn*64 + (lane & 3)*2;
    #pragma unroll
    for (int mb = 0; mb < 2; mb++) {
        #pragma unroll
        for (int nb = 0; nb < 8; nb++) {
            int col = cbase + nb*8;
            float bv0 = 0.0f, bv1 = 0.0f;
            if (bias) { bv0 = bias[col]; bv1 = bias[col+1]; }
            float v0 = acc[mb][nb][0] + bv0, v1 = acc[mb][nb][1] + bv1;
            float v2 = acc[mb][nb][2] + bv0, v3 = acc[mb][nb][3] + bv1;
            if (act) { v0 = silu_f(v0); v1 = silu_f(v1); v2 = silu_f(v2); v3 = silu_f(v3); }
            int r0 = rbase + mb*16;
            *(float2*)&C[(size_t)r0*ldc + col]     = make_float2(v0, v1);
            *(float2*)&C[(size_t)(r0+8)*ldc + col] = make_float2(v2, v3);
        }
    }
}

// ---------------- LayerNorm ---------------------------------------------------
__global__ void ln_kernel(const float* __restrict__ x,
                          const float* __restrict__ w,
                          const float* __restrict__ b) {
    int n = blockIdx.x;
    int t = threadIdx.x;
    float v = x[n*HSZ + t];
    __shared__ float red[256];
    red[t] = v; __syncthreads();
    for (int s = 128; s > 0; s >>= 1) { if (t < s) red[t] += red[t+s]; __syncthreads(); }
    float mu = red[0] * (1.0f/HSZ);
    __syncthreads();
    float d = v - mu;
    red[t] = d*d; __syncthreads();
    for (int s = 128; s > 0; s >>= 1) { if (t < s) red[t] += red[t+s]; __syncthreads(); }
    float var = red[0] * (1.0f/HSZ);
    g_xn[n*HSZ + t] = d * rsqrtf(var + 1e-5f) * w[t] + b[t];
}

// ---------------- fused attention: vatt = (silu(QK^T/sqrt(HD)) @ V)/N ---------
// grid (NSZ/32, NHSZ, BSZ), block 256. Q tile resident; loop K/V tiles.
__global__ void __launch_bounds__(256) attn_fused() {
    int b = blockIdx.z, h = blockIdx.y, i0 = blockIdx.x * 32;
    __shared__ float Qs[32][33], Ks[32][33], Vs[32][33], Ss[32][33];
    int tid = threadIdx.x;
    int ti = tid & 31;      // i within tile
    int g  = tid >> 5;      // 0..7

    for (int i = tid; i < 1024; i += 256) {
        int r = i >> 5, c = i & 31;
        Qs[r][c] = g_qkv[(size_t)(b*NSZ + i0 + r)*768 + h*HDSZ + c];
    }
    float acc[4] = {0.0f, 0.0f, 0.0f, 0.0f};

    for (int j0 = 0; j0 < NSZ; j0 += 32) {
        __syncthreads();
        for (int i = tid; i < 1024; i += 256) {
            int r = i >> 5, c = i & 31;
            const float* base = &g_qkv[(size_t)(b*NSZ + j0 + r)*768 + h*HDSZ + c];
            Ks[r][c] = base[256];
            Vs[r][c] = base[512];
        }
        __syncthreads();
        #pragma unroll
        for (int jj = 0; jj < 4; jj++) {
            int j = g*4 + jj;
            float s = 0.0f;
            #pragma unroll
            for (int c = 0; c < HDSZ; c++) s += Qs[ti][c] * Ks[j][c];
            Ss[ti][j] = silu_f(s * 0.1767766952966369f);
        }
        __syncthreads();
        #pragma unroll 8
        for (int j = 0; j < 32; j++) {
            float sv = Ss[ti][j];
            #pragma unroll
            for (int dd = 0; dd < 4; dd++) acc[dd] += sv * Vs[j][g*4 + dd];
        }
    }
    #pragma unroll
    for (int dd = 0; dd < 4; dd++)
        g_vatt[(size_t)(b*NSZ + i0 + ti)*HSZ + h*HDSZ + g*4 + dd] = acc[dd] * (1.0f/NSZ);
}

// ---------------- edge-wise / elementwise -------------------------------------
__global__ void cut_kernel(const float* __restrict__ r_ij) {
    int e = blockIdx.x*256 + threadIdx.x;
    if (e < ESZ) {
        float r = r_ij[e];
        float c = 0.5f * (cosf(3.14159265358979323846f * r / 5.0f) + 1.0f);
        g_cut[e] = (r < 5.0f) ? c : 0.0f;
    }
}

__global__ void concat_bias_kernel(const float* __restrict__ a, const float* __restrict__ b) {
    int i = blockIdx.x*256 + threadIdx.x;
    if (i < 256) g_b_dvfw[i] = a[i];
    else if (i < 512) g_b_dvfw[i] = b[i - 256];
}

// fused: compute v_j, write fp32 copy (for scatter) + bf16 hi/lo operand
__global__ void vjconv_kernel(const int* __restrict__ ei) {
    int kt = blockIdx.x, et = blockIdx.y;
    int seg = kt >> 2;
    bool lo = (seg == 1);
    int kc = (kt & 3) * 64;
    for (int i = threadIdx.x; i < 1024; i += 256) {
        int r = i >> 3, u = i & 7;
        int e = et*128 + r;
        int s = ei[e];
        float cv = g_cut[e];
        const float* vp = &g_vao[(size_t)s*HSZ + kc + u*8];
        const float* dp = &g_dvfw[(size_t)e*512 + kc + u*8];
        float4 a0 = *(const float4*)vp,       a1 = *(const float4*)(vp + 4);
        float4 b0 = *(const float4*)dp,       b1 = *(const float4*)(dp + 4);
        float f[8] = {a0.x*cv*b0.x, a0.y*cv*b0.y, a0.z*cv*b0.z, a0.w*cv*b0.w,
                      a1.x*cv*b1.x, a1.y*cv*b1.y, a1.z*cv*b1.z, a1.w*cv*b1.w};
        union { __nv_bfloat16 h[8]; uint4 u4; } o;
        #pragma unroll
        for (int j = 0; j < 8; j++) {
            __nv_bfloat16 hi = __float2bfloat16(f[j]);
            o.h[j] = lo ? __float2bfloat16(f[j] - __bfloat162float(hi)) : hi;
        }
        *(uint4*)(opA_vj + (size_t)e*KP + seg*256 + kc + u*8) = o.u4;
        if (seg == 0) {
            float* vj = &g_vj[(size_t)e*HSZ + kc + u*8];
            *(float4*)vj       = make_float4(f[0], f[1], f[2], f[3]);
            *(float4*)(vj + 4) = make_float4(f[4], f[5], f[6], f[7]);
        }
    }
}

__global__ void scatter_kernel(const int* __restrict__ ei,
                               const float* __restrict__ vecin,
                               const float* __restrict__ dij,
                               float* __restrict__ dvec_out) {
    int e = blockIdx.x;
    int h = threadIdx.x;
    int s = ei[e];
    int t = ei[ESZ + e];
    float s1 = g_s12[(size_t)e*512 + h];
    float s2 = g_s12[(size_t)e*512 + 256 + h];
    atomicAdd(&g_xagg[t*HSZ + h], g_vj[e*HSZ + h]);
    #pragma unroll
    for (int d = 0; d < VDSZ; d++) {
        float val = vecin[(size_t)(s*VDSZ + d)*HSZ + h] * s1 + s2 * dij[e*VDSZ + d];
        atomicAdd(&dvec_out[(size_t)(t*VDSZ + d)*HSZ + h], val);
    }
}

__global__ void vecsum_kernel(const float* __restrict__ vecin) {
    int idx = blockIdx.x*256 + threadIdx.x;
    int n = idx >> 8, h = idx & 255;
    float a = 0.0f;
    #pragma unroll
    for (int d = 0; d < VDSZ; d++) a += vecin[(size_t)(n*VDSZ + d)*HSZ + h];
    g_vecsumVD[idx] = a;
}

__global__ void zero_kernel(float* __restrict__ p, int n) {
    int i = blockIdx.x*256 + threadIdx.x;
    if (i < n) p[i] = 0.0f;
}

__global__ void dx_kernel(float* __restrict__ out_dx) {
    int idx = blockIdx.x*256 + threadIdx.x;
    int n = idx >> 8, h = idx & 255;
    out_dx[idx] = g_vecsum[idx] * g_o[(size_t)n*768 + 256 + h] + g_o[(size_t)n*768 + 512 + h];
}

__global__ void dvec_final_kernel(float* __restrict__ dvec_out) {
    int idx = blockIdx.x*256 + threadIdx.x;
    int n = idx >> 11;
    int d = (idx >> 8) & 7;
    int h = idx & 255;
    dvec_out[idx] += g_v3ts[(size_t)(n*VDSZ + d)*768 + h] * g_o[(size_t)n*768 + h];
}

__global__ void wdot_kernel(const int* __restrict__ ei,
                            const float* __restrict__ dij,
                            float* __restrict__ df_out) {
    int e = blockIdx.x;
    int h = threadIdx.x;
    int s = ei[e];
    int t = ei[ESZ + e];
    float p1 = 0.0f, p2 = 0.0f, ab = 0.0f, s2n = 0.0f;
    #pragma unroll
    for (int d = 0; d < VDSZ; d++) {
        float dd = dij[e*VDSZ + d];
        float a = g_v3ts[(size_t)(t*VDSZ + d)*768 + 256 + h];
        float b = g_v3ts[(size_t)(s*VDSZ + d)*768 + 512 + h];
        ab  += a*b;
        p1  += a*dd;
        p2  += b*dd;
        s2n += dd*dd;
    }
    float wdot = ab - p1*p2*(2.0f - s2n);
    df_out[(size_t)e*HSZ + h] = g_dvfw[(size_t)e*512 + 256 + h] * wdot;
}

// ---------------- host launcher ----------------------------------------------
extern "C" void kernel_launch(void* const* d_in, const int* in_sizes, int n_in,
                              void* d_out, int out_size) {
    const float* x    = (const float*)d_in[0];
    const float* vec  = (const float*)d_in[1];
    const int*   ei   = (const int*)  d_in[2];
    const float* r_ij = (const float*)d_in[3];
    const float* f_ij = (const float*)d_in[4];
    const float* d_ij = (const float*)d_in[5];
    const float* ln_w = (const float*)d_in[7];
    const float* ln_b = (const float*)d_in[8];
    const float* Wq   = (const float*)d_in[9];
    const float* Wk   = (const float*)d_in[10];
    const float* Wv   = (const float*)d_in[11];
    const float* Wao  = (const float*)d_in[12];
    const float* Wvec = (const float*)d_in[13];
    const float* Wdv  = (const float*)d_in[14];
    const float* bdv  = (const float*)d_in[15];
    const float* Ws   = (const float*)d_in[16];
    const float* bs   = (const float*)d_in[17];
    const float* Wo   = (const float*)d_in[18];
    const float* bo   = (const float*)d_in[19];
    const float* Wf   = (const float*)d_in[20];
    const float* bf   = (const float*)d_in[21];
    const float* Wsrc = (const float*)d_in[22];
    const float* Wtrg = (const float*)d_in[23];

    float* out      = (float*)d_out;
    float* out_dx   = out;
    float* out_dvec = out + BNN*HSZ;
    float* out_df   = out + BNN*HSZ + BNN*VDSZ*HSZ;

    float *p_xn, *p_qkv, *p_vatt, *p_vao, *p_dvfw, *p_vsVD, *p_vsum,
          *p_v3ts, *p_s12, *p_xagg, *p_o, *p_bdvfw;
    cudaGetSymbolAddress((void**)&p_xn,   g_xn);
    cudaGetSymbolAddress((void**)&p_qkv,  g_qkv);
    cudaGetSymbolAddress((void**)&p_vatt, g_vatt);
    cudaGetSymbolAddress((void**)&p_vao,  g_vao);
    cudaGetSymbolAddress((void**)&p_dvfw, g_dvfw);
    cudaGetSymbolAddress((void**)&p_vsVD, g_vecsumVD);
    cudaGetSymbolAddress((void**)&p_vsum, g_vecsum);
    cudaGetSymbolAddress((void**)&p_v3ts, g_v3ts);
    cudaGetSymbolAddress((void**)&p_s12,  g_s12);
    cudaGetSymbolAddress((void**)&p_xagg, g_xagg);
    cudaGetSymbolAddress((void**)&p_o,    g_o);
    cudaGetSymbolAddress((void**)&p_bdvfw, g_b_dvfw);

    __nv_bfloat16 *pA_xn, *pA_vatt, *pA_vsVD, *pA_xagg, *pA_fij, *pA_vec, *pA_vj;
    __nv_bfloat16 *pB_qkv, *pB_Wao, *pB_dvfw, *pB_Wv1, *pB_v3ts, *pB_Ws, *pB_Wo;
    cudaGetSymbolAddress((void**)&pA_xn,   opA_xn);
    cudaGetSymbolAddress((void**)&pA_vatt, opA_vatt);
    cudaGetSymbolAddress((void**)&pA_vsVD, opA_vsVD);
    cudaGetSymbolAddress((void**)&pA_xagg, opA_xagg);
    cudaGetSymbolAddress((void**)&pA_fij,  opA_fij);
    cudaGetSymbolAddress((void**)&pA_vec,  opA_vec);
    cudaGetSymbolAddress((void**)&pA_vj,   opA_vj);
    cudaGetSymbolAddress((void**)&pB_qkv,  opB_qkv);
    cudaGetSymbolAddress((void**)&pB_Wao,  opB_Wao);
    cudaGetSymbolAddress((void**)&pB_dvfw, opB_dvfw);
    cudaGetSymbolAddress((void**)&pB_Wv1,  opB_Wv1);
    cudaGetSymbolAddress((void**)&pB_v3ts, opB_v3ts);
    cudaGetSymbolAddress((void**)&pB_Ws,   opB_Ws);
    cudaGetSymbolAddress((void**)&pB_Wo,   opB_Wo);

    // ---- all weight conversions in ONE coalesced kernel ----
    conv_weights<<<240, 256>>>(Wq, Wk, Wv, Wao, Wdv, Wf, Wvec, Wtrg, Wsrc, Ws, Wo,
                               pB_qkv, pB_Wao, pB_dvfw, pB_Wv1, pB_v3ts, pB_Ws, pB_Wo);
    concat_bias_kernel<<<2,256>>>(bdv, bf);

    // ---- node pipeline ----
    ln_kernel<<<BNN,256>>>(x, ln_w, ln_b);
    convA_kernel<<<dim3(12,16),256>>>(p_xn, pA_xn);
    gemm_mma<<<dim3(6,16),256>>>(pA_xn, pB_qkv, p_qkv, 768, nullptr, 0);

    attn_fused<<<dim3(NSZ/32, NHSZ, BSZ),256>>>();
    convA_kernel<<<dim3(12,16),256>>>(p_vatt, pA_vatt);
    gemm_mma<<<dim3(2,16),256>>>(pA_vatt, pB_Wao, p_vao, 256, nullptr, 0);

    // ---- edge pipeline ----
    convA_kernel<<<dim3(12,128),256>>>(f_ij, pA_fij);
    gemm_mma<<<dim3(4,128),256>>>(pA_fij, pB_dvfw, p_dvfw, 512, p_bdvfw, 1);

    vecsum_kernel<<<BNN*HSZ/256,256>>>(vec);
    convA_kernel<<<dim3(12,16),256>>>(p_vsVD, pA_vsVD);
    gemm_mma<<<dim3(2,16),256>>>(pA_vsVD, pB_Wv1, p_vsum, 256, nullptr, 0);

    convA_kernel<<<dim3(12,128),256>>>(vec, pA_vec);
    gemm_mma<<<dim3(6,128),256>>>(pA_vec, pB_v3ts, p_v3ts, 768, nullptr, 0);

    cut_kernel<<<ESZ/256,256>>>(r_ij);
    vjconv_kernel<<<dim3(12,128),256>>>(ei);
    gemm_mma<<<dim3(4,128),256>>>(pA_vj, pB_Ws, p_s12, 512, bs, 1);

    zero_kernel<<<(BNN*HSZ+255)/256,256>>>(p_xagg, BNN*HSZ);
    zero_kernel<<<(BNN*VDSZ*HSZ+255)/256,256>>>(out_dvec, BNN*VDSZ*HSZ);
    scatter_kernel<<<ESZ,256>>>(ei, vec, d_ij, out_dvec);

    convA_kernel<<<dim3(12,16),256>>>(p_xagg, pA_xagg);
    gemm_mma<<<dim3(6,16),256>>>(pA_xagg, pB_Wo, p_o, 768, bo, 0);

    dx_kernel<<<BNN*HSZ/256,256>>>(out_dx);
    dvec_final_kernel<<<BNN*VDSZ*HSZ/256,256>>>(out_dvec);
    wdot_kernel<<<ESZ,256>>>(ei, d_ij, out_df);
}

// round 7
// speedup vs baseline: 1.7471x; 1.1045x over previous
#include <cuda_runtime.h>
#include <cuda_bf16.h>
#include <cstdint>
#include <math.h>

#define BNN 2048
#define HSZ 256
#define ESZ 16384
#define BSZ 8
#define NSZ 256
#define NHSZ 8
#define HDSZ 32
#define VDSZ 8

#define KP 768                    // K' = 3*256 bf16 cols
#define KP_BYTES 1536

// ---------------- fp32 scratch ------------------------------------------------
__device__ float g_qkv[BNN*3*HSZ];
__device__ float g_vao[BNN*HSZ];
__device__ float g_dvfw[ESZ*2*HSZ];          // [dv | fw] (both silu'd)
__device__ float g_vecsum[BNN*HSZ];
__device__ float g_v3ts[ESZ*3*HSZ];          // [vec3 | vt | vs] (rows = BNN*VD)
__device__ float g_vj[ESZ*HSZ];
__device__ float g_s12[ESZ*2*HSZ];
__device__ float g_xagg[BNN*HSZ];
__device__ float g_o[BNN*3*HSZ];
__device__ float g_b_dvfw[2*HSZ];

// ---------------- bf16 operand scratch (row-major [rows][768]) ----------------
__device__ __nv_bfloat16 opA_xn  [BNN*KP];
__device__ __nv_bfloat16 opA_vatt[BNN*KP];
__device__ __nv_bfloat16 opA_vsVD[BNN*KP];
__device__ __nv_bfloat16 opA_xagg[BNN*KP];
__device__ __nv_bfloat16 opA_fij [ESZ*KP];
__device__ __nv_bfloat16 opA_vec [ESZ*KP];
__device__ __nv_bfloat16 opA_vj  [ESZ*KP];
__device__ __nv_bfloat16 opB_qkv [768*KP];
__device__ __nv_bfloat16 opB_Wao [256*KP];
__device__ __nv_bfloat16 opB_dvfw[512*KP];
__device__ __nv_bfloat16 opB_Wv1 [256*KP];
__device__ __nv_bfloat16 opB_v3ts[768*KP];
__device__ __nv_bfloat16 opB_Ws  [512*KP];
__device__ __nv_bfloat16 opB_Wo  [768*KP];

__device__ __forceinline__ float silu_f(float x) { return x / (1.0f + __expf(-x)); }

// ---------------- operand conversion A (fp32 -> bf16 hi/lo, row-major) --------
// A segments along K': [hi | lo | hi]; B segments: [hi | hi | lo]
__global__ void convA_kernel(const float* __restrict__ A, __nv_bfloat16* __restrict__ dst) {
    int kt = blockIdx.x, mt = blockIdx.y;
    bool lo = ((kt >> 2) == 1);
    int seg = kt >> 2;
    int kc = (kt & 3) * 64;
    for (int i = threadIdx.x; i < 1024; i += 256) {
        int r = i >> 3, u = i & 7;
        const float* src = A + (size_t)(mt*128 + r)*HSZ + kc + u*8;
        float4 f0 = *(const float4*)src;
        float4 f1 = *(const float4*)(src + 4);
        float f[8] = {f0.x, f0.y, f0.z, f0.w, f1.x, f1.y, f1.z, f1.w};
        union { __nv_bfloat16 h[8]; uint4 u4; } o;
        #pragma unroll
        for (int j = 0; j < 8; j++) {
            __nv_bfloat16 hi = __float2bfloat16(f[j]);
            o.h[j] = lo ? __float2bfloat16(f[j] - __bfloat162float(hi)) : hi;
        }
        *(uint4*)(dst + (size_t)(mt*128 + r)*KP + seg*256 + kc + u*8) = o.u4;
    }
}

// ---------------- fused weight conversion (coalesced) -------------------------
__global__ void __launch_bounds__(256) conv_weights(
    const float* __restrict__ Wq, const float* __restrict__ Wk, const float* __restrict__ Wv,
    const float* __restrict__ Wao, const float* __restrict__ Wdv, const float* __restrict__ Wf,
    const float* __restrict__ Wvec, const float* __restrict__ Wtrg, const float* __restrict__ Wsrc,
    const float* __restrict__ Ws, const float* __restrict__ Wo,
    __nv_bfloat16* __restrict__ dq, __nv_bfloat16* __restrict__ dao,
    __nv_bfloat16* __restrict__ ddvfw, __nv_bfloat16* __restrict__ dwv1,
    __nv_bfloat16* __restrict__ dv3ts, __nv_bfloat16* __restrict__ dws,
    __nv_bfloat16* __restrict__ dwo)
{
    int t = blockIdx.x;
    const float* src; __nv_bfloat16* dst; int ldb, colOff, ntn, local;
    if (t < 160) {
        int j = t >> 4; local = t & 15; ntn = 4;
        switch (j) {
            case 0: src = Wq;   dst = dq;                       ldb = 256; colOff = 0;   break;
            case 1: src = Wk;   dst = dq + (size_t)256*KP;      ldb = 256; colOff = 0;   break;
            case 2: src = Wv;   dst = dq + (size_t)512*KP;      ldb = 256; colOff = 0;   break;
            case 3: src = Wao;  dst = dao;                      ldb = 256; colOff = 0;   break;
            case 4: src = Wdv;  dst = ddvfw;                    ldb = 256; colOff = 0;   break;
            case 5: src = Wf;   dst = ddvfw + (size_t)256*KP;   ldb = 256; colOff = 0;   break;
            case 6: src = Wvec; dst = dwv1;                     ldb = 512; colOff = 0;   break;
            case 7: src = Wvec; dst = dv3ts;                    ldb = 512; colOff = 256; break;
            case 8: src = Wtrg; dst = dv3ts + (size_t)256*KP;   ldb = 256; colOff = 0;   break;
            default:src = Wsrc; dst = dv3ts + (size_t)512*KP;   ldb = 256; colOff = 0;   break;
        }
    } else if (t < 192) {
        local = t - 160; ntn = 8;
        src = Ws; dst = dws; ldb = 512; colOff = 0;
    } else {
        local = t - 192; ntn = 12;
        src = Wo; dst = dwo; ldb = 768; colOff = 0;
    }
    int nt = local % ntn;
    int kt = local / ntn;
    int base_k = kt * 64;
    int base_n = colOff + nt * 64;

    __shared__ float Wt[64][65];
    int tid = threadIdx.x;
    for (int i = tid; i < 4096; i += 256) {
        int r = i >> 6, c = i & 63;
        Wt[r][c] = src[(size_t)(base_k + r)*ldb + base_n + c];
    }
    __syncthreads();
    for (int i = tid; i < 2048; i += 256) {
        int c = i >> 5;
        int k2 = (i & 31) * 2;
        float v0 = Wt[k2][c], v1 = Wt[k2+1][c];
        __nv_bfloat16 h0 = __float2bfloat16(v0), h1 = __float2bfloat16(v1);
        __nv_bfloat16 l0 = __float2bfloat16(v0 - __bfloat162float(h0));
        __nv_bfloat16 l1 = __float2bfloat16(v1 - __bfloat162float(h1));
        union { __nv_bfloat16 h[2]; uint32_t u; } hp, lp;
        hp.h[0] = h0; hp.h[1] = h1; lp.h[0] = l0; lp.h[1] = l1;
        size_t ro = (size_t)(nt*64 + c)*KP + kt*64 + k2;
        *(uint32_t*)&dst[ro]       = hp.u;   // seg0 hi
        *(uint32_t*)&dst[ro + 256] = hp.u;   // seg1 hi
        *(uint32_t*)&dst[ro + 512] = lp.u;   // seg2 lo
    }
}

// ---------------- mma.sync bf16x3 GEMM, BK=64, 2 CTAs/SM ----------------------
#define SPITCH 144
#define STILE (128*SPITCH)        // 18432 per operand tile
#define SSTAGE (2*STILE)          // 36864 per stage
#define GEMM_SMEM (2*SSTAGE)      // 73728

__device__ __forceinline__ uint32_t smem_u32(const void* p) {
    uint32_t a;
    asm("{ .reg .u64 t; cvta.to.shared.u64 t, %1; cvt.u32.u64 %0, t; }" : "=r"(a) : "l"(p));
    return a;
}

__global__ void __launch_bounds__(256, 2) gemm_mma(
    const __nv_bfloat16* __restrict__ Aop, const __nv_bfloat16* __restrict__ Bop,
    float* __restrict__ C, int ldc, const float* __restrict__ bias, int act)
{
    extern __shared__ __align__(16) char smem[];
    int tid = threadIdx.x;
    int lane = tid & 31, wid = tid >> 5;
    int wm = wid & 3, wn = wid >> 2;
    int nt = blockIdx.x, mt = blockIdx.y;
    const char* gA = (const char*)Aop + (size_t)mt*128*KP_BYTES;
    const char* gB = (const char*)Bop + (size_t)nt*128*KP_BYTES;
    uint32_t sbase = smem_u32(smem);

    auto load_stage = [&](int buf, int s) {
        uint32_t dst0 = sbase + buf*SSTAGE;
        #pragma unroll
        for (int t = 0; t < 8; t++) {
            int ci = tid + t*256;            // 2048 chunks of 16B (1024 A + 1024 B)
            int isB = ci >> 10;
            int cc = ci & 1023;
            int row = cc >> 3, c = cc & 7;
            uint32_t dst = dst0 + isB*STILE + row*SPITCH + c*16;
            const char* src = (isB ? gB : gA) + (size_t)row*KP_BYTES + s*128 + c*16;
            asm volatile("cp.async.cg.shared.global [%0], [%1], 16;\n" :: "r"(dst), "l"(src));
        }
        asm volatile("cp.async.commit_group;\n");
    };

    float acc[2][8][4];
    #pragma unroll
    for (int i = 0; i < 2; i++)
        #pragma unroll
        for (int j = 0; j < 8; j++)
            #pragma unroll
            for (int k = 0; k < 4; k++) acc[i][j][k] = 0.0f;

    load_stage(0, 0);
    const int NS = KP/64;    // 12
    for (int s = 0; s < NS; s++) {
        int buf = s & 1;
        if (s + 1 < NS) {
            load_stage(buf ^ 1, s + 1);
            asm volatile("cp.async.wait_group 1;\n");
        } else {
            asm volatile("cp.async.wait_group 0;\n");
        }
        __syncthreads();
        uint32_t bA = sbase + buf*SSTAGE;
        uint32_t bB = bA + STILE;
        #pragma unroll
        for (int kk = 0; kk < 64; kk += 16) {
            uint32_t a[2][4];
            #pragma unroll
            for (int mb = 0; mb < 2; mb++) {
                uint32_t addr = bA + (wm*32 + mb*16 + (lane & 15))*SPITCH
                                   + (kk + ((lane >> 4) << 3))*2;
                asm volatile("ldmatrix.sync.aligned.m8n8.x4.shared.b16 {%0,%1,%2,%3}, [%4];"
                    : "=r"(a[mb][0]), "=r"(a[mb][1]), "=r"(a[mb][2]), "=r"(a[mb][3]) : "r"(addr));
            }
            uint32_t b[8][2];
            #pragma unroll
            for (int nb4 = 0; nb4 < 4; nb4++) {
                uint32_t r0, r1, r2, r3;
                uint32_t addr = bB + (wn*64 + nb4*16 + (lane & 15))*SPITCH
                                   + (kk + ((lane >> 4) << 3))*2;
                asm volatile("ldmatrix.sync.aligned.m8n8.x4.shared.b16 {%0,%1,%2,%3}, [%4];"
                    : "=r"(r0), "=r"(r1), "=r"(r2), "=r"(r3) : "r"(addr));
                b[nb4*2][0] = r0; b[nb4*2][1] = r2;
                b[nb4*2+1][0] = r1; b[nb4*2+1][1] = r3;
            }
            #pragma unroll
            for (int mb = 0; mb < 2; mb++)
                #pragma unroll
                for (int nb = 0; nb < 8; nb++)
                    asm volatile("mma.sync.aligned.m16n8k16.row.col.f32.bf16.bf16.f32 "
                        "{%0,%1,%2,%3}, {%4,%5,%6,%7}, {%8,%9}, {%0,%1,%2,%3};"
                        : "+f"(acc[mb][nb][0]), "+f"(acc[mb][nb][1]),
                          "+f"(acc[mb][nb][2]), "+f"(acc[mb][nb][3])
                        : "r"(a[mb][0]), "r"(a[mb][1]), "r"(a[mb][2]), "r"(a[mb][3]),
                          "r"(b[nb][0]), "r"(b[nb][1]));
        }
        __syncthreads();
    }

    int rbase = mt*128 + wm*32 + (lane >> 2);
    int cbase = nt*128 + wn*64 + (lane & 3)*2;
    #pragma unroll
    for (int mb = 0; mb < 2; mb++) {
        #pragma unroll
        for (int nb = 0; nb < 8; nb++) {
            int col = cbase + nb*8;
            float bv0 = 0.0f, bv1 = 0.0f;
            if (bias) { bv0 = bias[col]; bv1 = bias[col+1]; }
            float v0 = acc[mb][nb][0] + bv0, v1 = acc[mb][nb][1] + bv1;
            float v2 = acc[mb][nb][2] + bv0, v3 = acc[mb][nb][3] + bv1;
            if (act) { v0 = silu_f(v0); v1 = silu_f(v1); v2 = silu_f(v2); v3 = silu_f(v3); }
            int r0 = rbase + mb*16;
            *(float2*)&C[(size_t)r0*ldc + col]     = make_float2(v0, v1);
            *(float2*)&C[(size_t)(r0+8)*ldc + col] = make_float2(v2, v3);
        }
    }
}

// ---------------- LayerNorm (fused bf16 operand write) ------------------------
__global__ void ln_kernel(const float* __restrict__ x,
                          const float* __restrict__ w,
                          const float* __restrict__ b) {
    int n = blockIdx.x;
    int t = threadIdx.x;
    float v = x[n*HSZ + t];
    __shared__ float red[256];
    red[t] = v; __syncthreads();
    for (int s = 128; s > 0; s >>= 1) { if (t < s) red[t] += red[t+s]; __syncthreads(); }
    float mu = red[0] * (1.0f/HSZ);
    __syncthreads();
    float d = v - mu;
    red[t] = d*d; __syncthreads();
    for (int s = 128; s > 0; s >>= 1) { if (t < s) red[t] += red[t+s]; __syncthreads(); }
    float var = red[0] * (1.0f/HSZ);
    float xn = d * rsqrtf(var + 1e-5f) * w[t] + b[t];
    __nv_bfloat16 hi = __float2bfloat16(xn);
    __nv_bfloat16 lo = __float2bfloat16(xn - __bfloat162float(hi));
    __nv_bfloat16* dst = opA_xn + (size_t)n*KP + t;
    dst[0]   = hi;
    dst[256] = lo;
    dst[512] = hi;
}

// ---------------- fused attention (writes bf16 operand directly) --------------
__global__ void __launch_bounds__(256) attn_fused() {
    int b = blockIdx.z, h = blockIdx.y, i0 = blockIdx.x * 32;
    __shared__ float Qs[32][33], Ks[32][33], Vs[32][33], Ss[32][33];
    int tid = threadIdx.x;
    int ti = tid & 31;
    int g  = tid >> 5;

    for (int i = tid; i < 1024; i += 256) {
        int r = i >> 5, c = i & 31;
        Qs[r][c] = g_qkv[(size_t)(b*NSZ + i0 + r)*768 + h*HDSZ + c];
    }
    float acc[4] = {0.0f, 0.0f, 0.0f, 0.0f};

    for (int j0 = 0; j0 < NSZ; j0 += 32) {
        __syncthreads();
        for (int i = tid; i < 1024; i += 256) {
            int r = i >> 5, c = i & 31;
            const float* base = &g_qkv[(size_t)(b*NSZ + j0 + r)*768 + h*HDSZ + c];
            Ks[r][c] = base[256];
            Vs[r][c] = base[512];
        }
        __syncthreads();
        #pragma unroll
        for (int jj = 0; jj < 4; jj++) {
            int j = g*4 + jj;
            float s = 0.0f;
            #pragma unroll
            for (int c = 0; c < HDSZ; c++) s += Qs[ti][c] * Ks[j][c];
            Ss[ti][j] = silu_f(s * 0.1767766952966369f);
        }
        __syncthreads();
        #pragma unroll 8
        for (int j = 0; j < 32; j++) {
            float sv = Ss[ti][j];
            #pragma unroll
            for (int dd = 0; dd < 4; dd++) acc[dd] += sv * Vs[j][g*4 + dd];
        }
    }
    union { __nv_bfloat16 h[2]; uint32_t u; } hp0, hp1, lp0, lp1;
    #pragma unroll
    for (int dd = 0; dd < 4; dd++) {
        float v = acc[dd] * (1.0f/NSZ);
        __nv_bfloat16 hi = __float2bfloat16(v);
        __nv_bfloat16 lo = __float2bfloat16(v - __bfloat162float(hi));
        if (dd < 2) { hp0.h[dd] = hi; lp0.h[dd] = lo; }
        else        { hp1.h[dd-2] = hi; lp1.h[dd-2] = lo; }
    }
    size_t ro = (size_t)(b*NSZ + i0 + ti)*KP + h*HDSZ + g*4;
    *(uint32_t*)&opA_vatt[ro]           = hp0.u;
    *(uint32_t*)&opA_vatt[ro + 2]       = hp1.u;
    *(uint32_t*)&opA_vatt[ro + 256]     = lp0.u;
    *(uint32_t*)&opA_vatt[ro + 258]     = lp1.u;
    *(uint32_t*)&opA_vatt[ro + 512]     = hp0.u;
    *(uint32_t*)&opA_vatt[ro + 514]     = hp1.u;
}

// ---------------- edge-wise / elementwise -------------------------------------
__global__ void concat_bias_kernel(const float* __restrict__ a, const float* __restrict__ b) {
    int i = blockIdx.x*256 + threadIdx.x;
    if (i < 256) g_b_dvfw[i] = a[i];
    else if (i < 512) g_b_dvfw[i] = b[i - 256];
}

// fused: cutoff + v_j compute, fp32 copy + bf16 hi/lo operand
__global__ void vjconv_kernel(const int* __restrict__ ei, const float* __restrict__ r_ij) {
    int kt = blockIdx.x, et = blockIdx.y;
    int seg = kt >> 2;
    bool lo = (seg == 1);
    int kc = (kt & 3) * 64;
    for (int i = threadIdx.x; i < 1024; i += 256) {
        int r = i >> 3, u = i & 7;
        int e = et*128 + r;
        int s = ei[e];
        float rr = r_ij[e];
        float cv = (rr < 5.0f) ? 0.5f * (cosf(3.14159265358979323846f * rr / 5.0f) + 1.0f) : 0.0f;
        const float* vp = &g_vao[(size_t)s*HSZ + kc + u*8];
        const float* dp = &g_dvfw[(size_t)e*512 + kc + u*8];
        float4 a0 = *(const float4*)vp,       a1 = *(const float4*)(vp + 4);
        float4 b0 = *(const float4*)dp,       b1 = *(const float4*)(dp + 4);
        float f[8] = {a0.x*cv*b0.x, a0.y*cv*b0.y, a0.z*cv*b0.z, a0.w*cv*b0.w,
                      a1.x*cv*b1.x, a1.y*cv*b1.y, a1.z*cv*b1.z, a1.w*cv*b1.w};
        union { __nv_bfloat16 h[8]; uint4 u4; } o;
        #pragma unroll
        for (int j = 0; j < 8; j++) {
            __nv_bfloat16 hi = __float2bfloat16(f[j]);
            o.h[j] = lo ? __float2bfloat16(f[j] - __bfloat162float(hi)) : hi;
        }
        *(uint4*)(opA_vj + (size_t)e*KP + seg*256 + kc + u*8) = o.u4;
        if (seg == 0) {
            float* vj = &g_vj[(size_t)e*HSZ + kc + u*8];
            *(float4*)vj       = make_float4(f[0], f[1], f[2], f[3]);
            *(float4*)(vj + 4) = make_float4(f[4], f[5], f[6], f[7]);
        }
    }
}

__global__ void scatter_kernel(const int* __restrict__ ei,
                               const float* __restrict__ vecin,
                               const float* __restrict__ dij,
                               float* __restrict__ dvec_out) {
    int e = blockIdx.x;
    int h = threadIdx.x;
    int s = ei[e];
    int t = ei[ESZ + e];
    float s1 = g_s12[(size_t)e*512 + h];
    float s2 = g_s12[(size_t)e*512 + 256 + h];
    atomicAdd(&g_xagg[t*HSZ + h], g_vj[e*HSZ + h]);
    #pragma unroll
    for (int d = 0; d < VDSZ; d++) {
        float val = vecin[(size_t)(s*VDSZ + d)*HSZ + h] * s1 + s2 * dij[e*VDSZ + d];
        atomicAdd(&dvec_out[(size_t)(t*VDSZ + d)*HSZ + h], val);
    }
}

__global__ void vecsum_kernel(const float* __restrict__ vecin) {
    int idx = blockIdx.x*256 + threadIdx.x;
    int n = idx >> 8, h = idx & 255;
    float a = 0.0f;
    #pragma unroll
    for (int d = 0; d < VDSZ; d++) a += vecin[(size_t)(n*VDSZ + d)*HSZ + h];
    __nv_bfloat16 hi = __float2bfloat16(a);
    __nv_bfloat16 lo = __float2bfloat16(a - __bfloat162float(hi));
    __nv_bfloat16* dst = opA_vsVD + (size_t)n*KP + h;
    dst[0]   = hi;
    dst[256] = lo;
    dst[512] = hi;
}

__global__ void dx_kernel(float* __restrict__ out_dx) {
    int idx = blockIdx.x*256 + threadIdx.x;
    int n = idx >> 8, h = idx & 255;
    out_dx[idx] = g_vecsum[idx] * g_o[(size_t)n*768 + 256 + h] + g_o[(size_t)n*768 + 512 + h];
}

__global__ void dvec_final_kernel(float* __restrict__ dvec_out) {
    int idx = blockIdx.x*256 + threadIdx.x;
    int n = idx >> 11;
    int d = (idx >> 8) & 7;
    int h = idx & 255;
    dvec_out[idx] += g_v3ts[(size_t)(n*VDSZ + d)*768 + h] * g_o[(size_t)n*768 + h];
}

__global__ void wdot_kernel(const int* __restrict__ ei,
                            const float* __restrict__ dij,
                            float* __restrict__ df_out) {
    int e = blockIdx.x;
    int h = threadIdx.x;
    int s = ei[e];
    int t = ei[ESZ + e];
    float p1 = 0.0f, p2 = 0.0f, ab = 0.0f, s2n = 0.0f;
    #pragma unroll
    for (int d = 0; d < VDSZ; d++) {
        float dd = dij[e*VDSZ + d];
        float a = g_v3ts[(size_t)(t*VDSZ + d)*768 + 256 + h];
        float b = g_v3ts[(size_t)(s*VDSZ + d)*768 + 512 + h];
        ab  += a*b;
        p1  += a*dd;
        p2  += b*dd;
        s2n += dd*dd;
    }
    float wdot = ab - p1*p2*(2.0f - s2n);
    df_out[(size_t)e*HSZ + h] = g_dvfw[(size_t)e*512 + 256 + h] * wdot;
}

// ---------------- host launcher ----------------------------------------------
extern "C" void kernel_launch(void* const* d_in, const int* in_sizes, int n_in,
                              void* d_out, int out_size) {
    const float* x    = (const float*)d_in[0];
    const float* vec  = (const float*)d_in[1];
    const int*   ei   = (const int*)  d_in[2];
    const float* r_ij = (const float*)d_in[3];
    const float* f_ij = (const float*)d_in[4];
    const float* d_ij = (const float*)d_in[5];
    const float* ln_w = (const float*)d_in[7];
    const float* ln_b = (const float*)d_in[8];
    const float* Wq   = (const float*)d_in[9];
    const float* Wk   = (const float*)d_in[10];
    const float* Wv   = (const float*)d_in[11];
    const float* Wao  = (const float*)d_in[12];
    const float* Wvec = (const float*)d_in[13];
    const float* Wdv  = (const float*)d_in[14];
    const float* bdv  = (const float*)d_in[15];
    const float* Ws   = (const float*)d_in[16];
    const float* bs   = (const float*)d_in[17];
    const float* Wo   = (const float*)d_in[18];
    const float* bo   = (const float*)d_in[19];
    const float* Wf   = (const float*)d_in[20];
    const float* bf   = (const float*)d_in[21];
    const float* Wsrc = (const float*)d_in[22];
    const float* Wtrg = (const float*)d_in[23];

    float* out      = (float*)d_out;
    float* out_dx   = out;
    float* out_dvec = out + BNN*HSZ;
    float* out_df   = out + BNN*HSZ + BNN*VDSZ*HSZ;

    float *p_qkv, *p_vao, *p_dvfw, *p_vsum, *p_v3ts, *p_s12, *p_xagg, *p_o, *p_bdvfw;
    cudaGetSymbolAddress((void**)&p_qkv,  g_qkv);
    cudaGetSymbolAddress((void**)&p_vao,  g_vao);
    cudaGetSymbolAddress((void**)&p_dvfw, g_dvfw);
    cudaGetSymbolAddress((void**)&p_vsum, g_vecsum);
    cudaGetSymbolAddress((void**)&p_v3ts, g_v3ts);
    cudaGetSymbolAddress((void**)&p_s12,  g_s12);
    cudaGetSymbolAddress((void**)&p_xagg, g_xagg);
    cudaGetSymbolAddress((void**)&p_o,    g_o);
    cudaGetSymbolAddress((void**)&p_bdvfw, g_b_dvfw);

    __nv_bfloat16 *pA_xn, *pA_vatt, *pA_vsVD, *pA_xagg, *pA_fij, *pA_vec, *pA_vj;
    __nv_bfloat16 *pB_qkv, *pB_Wao, *pB_dvfw, *pB_Wv1, *pB_v3ts, *pB_Ws, *pB_Wo;
    cudaGetSymbolAddress((void**)&pA_xn,   opA_xn);
    cudaGetSymbolAddress((void**)&pA_vatt, opA_vatt);
    cudaGetSymbolAddress((void**)&pA_vsVD, opA_vsVD);
    cudaGetSymbolAddress((void**)&pA_xagg, opA_xagg);
    cudaGetSymbolAddress((void**)&pA_fij,  opA_fij);
    cudaGetSymbolAddress((void**)&pA_vec,  opA_vec);
    cudaGetSymbolAddress((void**)&pA_vj,   opA_vj);
    cudaGetSymbolAddress((void**)&pB_qkv,  opB_qkv);
    cudaGetSymbolAddress((void**)&pB_Wao,  opB_Wao);
    cudaGetSymbolAddress((void**)&pB_dvfw, opB_dvfw);
    cudaGetSymbolAddress((void**)&pB_Wv1,  opB_Wv1);
    cudaGetSymbolAddress((void**)&pB_v3ts, opB_v3ts);
    cudaGetSymbolAddress((void**)&pB_Ws,   opB_Ws);
    cudaGetSymbolAddress((void**)&pB_Wo,   opB_Wo);

    cudaFuncSetAttribute(gemm_mma, cudaFuncAttributeMaxDynamicSharedMemorySize, GEMM_SMEM);

    // ---- weight conversions ----
    conv_weights<<<240, 256>>>(Wq, Wk, Wv, Wao, Wdv, Wf, Wvec, Wtrg, Wsrc, Ws, Wo,
                               pB_qkv, pB_Wao, pB_dvfw, pB_Wv1, pB_v3ts, pB_Ws, pB_Wo);
    concat_bias_kernel<<<2,256>>>(bdv, bf);

    // ---- node pipeline ----
    ln_kernel<<<BNN,256>>>(x, ln_w, ln_b);
    gemm_mma<<<dim3(6,16),256,GEMM_SMEM>>>(pA_xn, pB_qkv, p_qkv, 768, nullptr, 0);

    attn_fused<<<dim3(NSZ/32, NHSZ, BSZ),256>>>();
    gemm_mma<<<dim3(2,16),256,GEMM_SMEM>>>(pA_vatt, pB_Wao, p_vao, 256, nullptr, 0);

    // ---- edge pipeline ----
    convA_kernel<<<dim3(12,128),256>>>(f_ij, pA_fij);
    gemm_mma<<<dim3(4,128),256,GEMM_SMEM>>>(pA_fij, pB_dvfw, p_dvfw, 512, p_bdvfw, 1);

    vecsum_kernel<<<BNN*HSZ/256,256>>>(vec);
    gemm_mma<<<dim3(2,16),256,GEMM_SMEM>>>(pA_vsVD, pB_Wv1, p_vsum, 256, nullptr, 0);

    convA_kernel<<<dim3(12,128),256>>>(vec, pA_vec);
    gemm_mma<<<dim3(6,128),256,GEMM_SMEM>>>(pA_vec, pB_v3ts, p_v3ts, 768, nullptr, 0);

    vjconv_kernel<<<dim3(12,128),256>>>(ei, r_ij);
    gemm_mma<<<dim3(4,128),256,GEMM_SMEM>>>(pA_vj, pB_Ws, p_s12, 512, bs, 1);

    cudaMemsetAsync(p_xagg, 0, (size_t)BNN*HSZ*sizeof(float));
    cudaMemsetAsync(out_dvec, 0, (size_t)BNN*VDSZ*HSZ*sizeof(float));
    scatter_kernel<<<ESZ,256>>>(ei, vec, d_ij, out_dvec);

    convA_kernel<<<dim3(12,16),256>>>(p_xagg, pA_xagg);
    gemm_mma<<<dim3(6,16),256,GEMM_SMEM>>>(pA_xagg, pB_Wo, p_o, 768, bo, 0);

    dx_kernel<<<BNN*HSZ/256,256>>>(out_dx);
    dvec_final_kernel<<<BNN*VDSZ*HSZ/256,256>>>(out_dvec);
    wdot_kernel<<<ESZ,256>>>(ei, d_ij, out_df);
}

// round 9
// speedup vs baseline: 1.8728x; 1.0720x over previous
#include <cuda_runtime.h>
#include <cuda_bf16.h>
#include <cstdint>
#include <math.h>

#define BNN 2048
#define HSZ 256
#define ESZ 16384
#define BSZ 8
#define NSZ 256
#define NHSZ 8
#define HDSZ 32
#define VDSZ 8

#define KP 768                    // K' = 3*256 bf16 cols
#define KP_BYTES 1536

// ---------------- fp32 scratch ------------------------------------------------
__device__ float g_qkv[BNN*3*HSZ];
__device__ float g_vao[BNN*HSZ];
__device__ float g_dvfw[ESZ*2*HSZ];          // [dv | fw] (both silu'd)
__device__ float g_vecsum[BNN*HSZ];
__device__ float g_v3ts[ESZ*3*HSZ];          // [vec3 | vt | vs] (rows = BNN*VD)
__device__ float g_vj[ESZ*HSZ];
__device__ float g_s12[ESZ*2*HSZ];
__device__ float g_xagg[BNN*HSZ];
__device__ float g_o[BNN*3*HSZ];
__device__ float g_b_dvfw[2*HSZ];

// ---------------- bf16 operand scratch (row-major [rows][768]) ----------------
__device__ __nv_bfloat16 opA_xn  [BNN*KP];
__device__ __nv_bfloat16 opA_vatt[BNN*KP];
__device__ __nv_bfloat16 opA_vsVD[BNN*KP];
__device__ __nv_bfloat16 opA_xagg[BNN*KP];
__device__ __nv_bfloat16 opA_fij [ESZ*KP];
__device__ __nv_bfloat16 opA_vec [ESZ*KP];
__device__ __nv_bfloat16 opA_vj  [ESZ*KP];
__device__ __nv_bfloat16 opB_qkv [768*KP];
__device__ __nv_bfloat16 opB_Wao [256*KP];
__device__ __nv_bfloat16 opB_dvfw[512*KP];
__device__ __nv_bfloat16 opB_Wv1 [256*KP];
__device__ __nv_bfloat16 opB_v3ts[768*KP];
__device__ __nv_bfloat16 opB_Ws  [512*KP];
__device__ __nv_bfloat16 opB_Wo  [768*KP];

__device__ __forceinline__ float silu_f(float x) { return x / (1.0f + __expf(-x)); }

// ---------------- operand conversion A (fp32 -> bf16 hi/lo, row-major) --------
__global__ void convA_kernel(const float* __restrict__ A, __nv_bfloat16* __restrict__ dst) {
    int kt = blockIdx.x, mt = blockIdx.y;
    bool lo = ((kt >> 2) == 1);
    int seg = kt >> 2;
    int kc = (kt & 3) * 64;
    for (int i = threadIdx.x; i < 1024; i += 256) {
        int r = i >> 3, u = i & 7;
        const float* src = A + (size_t)(mt*128 + r)*HSZ + kc + u*8;
        float4 f0 = *(const float4*)src;
        float4 f1 = *(const float4*)(src + 4);
        float f[8] = {f0.x, f0.y, f0.z, f0.w, f1.x, f1.y, f1.z, f1.w};
        union { __nv_bfloat16 h[8]; uint4 u4; } o;
        #pragma unroll
        for (int j = 0; j < 8; j++) {
            __nv_bfloat16 hi = __float2bfloat16(f[j]);
            o.h[j] = lo ? __float2bfloat16(f[j] - __bfloat162float(hi)) : hi;
        }
        *(uint4*)(dst + (size_t)(mt*128 + r)*KP + seg*256 + kc + u*8) = o.u4;
    }
}

// ---------------- fused weight conversion (coalesced) -------------------------
__global__ void __launch_bounds__(256) conv_weights(
    const float* __restrict__ Wq, const float* __restrict__ Wk, const float* __restrict__ Wv,
    const float* __restrict__ Wao, const float* __restrict__ Wdv, const float* __restrict__ Wf,
    const float* __restrict__ Wvec, const float* __restrict__ Wtrg, const float* __restrict__ Wsrc,
    const float* __restrict__ Ws, const float* __restrict__ Wo,
    __nv_bfloat16* __restrict__ dq, __nv_bfloat16* __restrict__ dao,
    __nv_bfloat16* __restrict__ ddvfw, __nv_bfloat16* __restrict__ dwv1,
    __nv_bfloat16* __restrict__ dv3ts, __nv_bfloat16* __restrict__ dws,
    __nv_bfloat16* __restrict__ dwo)
{
    int t = blockIdx.x;
    const float* src; __nv_bfloat16* dst; int ldb, colOff, ntn, local;
    if (t < 160) {
        int j = t >> 4; local = t & 15; ntn = 4;
        switch (j) {
            case 0: src = Wq;   dst = dq;                       ldb = 256; colOff = 0;   break;
            case 1: src = Wk;   dst = dq + (size_t)256*KP;      ldb = 256; colOff = 0;   break;
            case 2: src = Wv;   dst = dq + (size_t)512*KP;      ldb = 256; colOff = 0;   break;
            case 3: src = Wao;  dst = dao;                      ldb = 256; colOff = 0;   break;
            case 4: src = Wdv;  dst = ddvfw;                    ldb = 256; colOff = 0;   break;
            case 5: src = Wf;   dst = ddvfw + (size_t)256*KP;   ldb = 256; colOff = 0;   break;
            case 6: src = Wvec; dst = dwv1;                     ldb = 512; colOff = 0;   break;
            case 7: src = Wvec; dst = dv3ts;                    ldb = 512; colOff = 256; break;
            case 8: src = Wtrg; dst = dv3ts + (size_t)256*KP;   ldb = 256; colOff = 0;   break;
            default:src = Wsrc; dst = dv3ts + (size_t)512*KP;   ldb = 256; colOff = 0;   break;
        }
    } else if (t < 192) {
        local = t - 160; ntn = 8;
        src = Ws; dst = dws; ldb = 512; colOff = 0;
    } else {
        local = t - 192; ntn = 12;
        src = Wo; dst = dwo; ldb = 768; colOff = 0;
    }
    int nt = local % ntn;
    int kt = local / ntn;
    int base_k = kt * 64;
    int base_n = colOff + nt * 64;

    __shared__ float Wt[64][65];
    int tid = threadIdx.x;
    for (int i = tid; i < 4096; i += 256) {
        int r = i >> 6, c = i & 63;
        Wt[r][c] = src[(size_t)(base_k + r)*ldb + base_n + c];
    }
    __syncthreads();
    for (int i = tid; i < 2048; i += 256) {
        int c = i >> 5;
        int k2 = (i & 31) * 2;
        float v0 = Wt[k2][c], v1 = Wt[k2+1][c];
        __nv_bfloat16 h0 = __float2bfloat16(v0), h1 = __float2bfloat16(v1);
        __nv_bfloat16 l0 = __float2bfloat16(v0 - __bfloat162float(h0));
        __nv_bfloat16 l1 = __float2bfloat16(v1 - __bfloat162float(h1));
        union { __nv_bfloat16 h[2]; uint32_t u; } hp, lp;
        hp.h[0] = h0; hp.h[1] = h1; lp.h[0] = l0; lp.h[1] = l1;
        size_t ro = (size_t)(nt*64 + c)*KP + kt*64 + k2;
        *(uint32_t*)&dst[ro]       = hp.u;
        *(uint32_t*)&dst[ro + 256] = hp.u;
        *(uint32_t*)&dst[ro + 512] = lp.u;
    }
}

// ---------------- mma.sync bf16x3 GEMM core (BK=64) ---------------------------
#define SPITCH 144
#define STILE (128*SPITCH)        // 18432 per operand tile
#define SSTAGE (2*STILE)          // 36864 per stage
#define GEMM_SMEM (2*SSTAGE)      // 73728

__device__ __forceinline__ uint32_t smem_u32(const void* p) {
    uint32_t a;
    asm("{ .reg .u64 t; cvta.to.shared.u64 t, %1; cvt.u32.u64 %0, t; }" : "=r"(a) : "l"(p));
    return a;
}

__device__ __forceinline__ void gemm_body(
    const __nv_bfloat16* __restrict__ Aop, const __nv_bfloat16* __restrict__ Bop,
    float* __restrict__ C, int ldc, const float* __restrict__ bias, int act,
    int nt, int mt)
{
    extern __shared__ __align__(16) char smem[];
    int tid = threadIdx.x;
    int lane = tid & 31, wid = tid >> 5;
    int wm = wid & 3, wn = wid >> 2;
    const char* gA = (const char*)Aop + (size_t)mt*128*KP_BYTES;
    const char* gB = (const char*)Bop + (size_t)nt*128*KP_BYTES;
    uint32_t sbase = smem_u32(smem);

    auto load_stage = [&](int buf, int s) {
        uint32_t dst0 = sbase + buf*SSTAGE;
        #pragma unroll
        for (int t = 0; t < 8; t++) {
            int ci = tid + t*256;
            int isB = ci >> 10;
            int cc = ci & 1023;
            int row = cc >> 3, c = cc & 7;
            uint32_t dst = dst0 + isB*STILE + row*SPITCH + c*16;
            const char* src = (isB ? gB : gA) + (size_t)row*KP_BYTES + s*128 + c*16;
            asm volatile("cp.async.cg.shared.global [%0], [%1], 16;\n" :: "r"(dst), "l"(src));
        }
        asm volatile("cp.async.commit_group;\n");
    };

    float acc[2][8][4];
    #pragma unroll
    for (int i = 0; i < 2; i++)
        #pragma unroll
        for (int j = 0; j < 8; j++)
            #pragma unroll
            for (int k = 0; k < 4; k++) acc[i][j][k] = 0.0f;

    load_stage(0, 0);
    const int NS = KP/64;    // 12
    for (int s = 0; s < NS; s++) {
        int buf = s & 1;
        if (s + 1 < NS) {
            load_stage(buf ^ 1, s + 1);
            asm volatile("cp.async.wait_group 1;\n");
        } else {
            asm volatile("cp.async.wait_group 0;\n");
        }
        __syncthreads();
        uint32_t bA = sbase + buf*SSTAGE;
        uint32_t bB = bA + STILE;
        #pragma unroll
        for (int kk = 0; kk < 64; kk += 16) {
            uint32_t a[2][4];
            #pragma unroll
            for (int mb = 0; mb < 2; mb++) {
                uint32_t addr = bA + (wm*32 + mb*16 + (lane & 15))*SPITCH
                                   + (kk + ((lane >> 4) << 3))*2;
                asm volatile("ldmatrix.sync.aligned.m8n8.x4.shared.b16 {%0,%1,%2,%3}, [%4];"
                    : "=r"(a[mb][0]), "=r"(a[mb][1]), "=r"(a[mb][2]), "=r"(a[mb][3]) : "r"(addr));
            }
            uint32_t b[8][2];
            #pragma unroll
            for (int nb4 = 0; nb4 < 4; nb4++) {
                uint32_t r0, r1, r2, r3;
                uint32_t addr = bB + (wn*64 + nb4*16 + (lane & 15))*SPITCH
                                   + (kk + ((lane >> 4) << 3))*2;
                asm volatile("ldmatrix.sync.aligned.m8n8.x4.shared.b16 {%0,%1,%2,%3}, [%4];"
                    : "=r"(r0), "=r"(r1), "=r"(r2), "=r"(r3) : "r"(addr));
                b[nb4*2][0] = r0; b[nb4*2][1] = r2;
                b[nb4*2+1][0] = r1; b[nb4*2+1][1] = r3;
            }
            #pragma unroll
            for (int mb = 0; mb < 2; mb++)
                #pragma unroll
                for (int nb = 0; nb < 8; nb++)
                    asm volatile("mma.sync.aligned.m16n8k16.row.col.f32.bf16.bf16.f32 "
                        "{%0,%1,%2,%3}, {%4,%5,%6,%7}, {%8,%9}, {%0,%1,%2,%3};"
                        : "+f"(acc[mb][nb][0]), "+f"(acc[mb][nb][1]),
                          "+f"(acc[mb][nb][2]), "+f"(acc[mb][nb][3])
                        : "r"(a[mb][0]), "r"(a[mb][1]), "r"(a[mb][2]), "r"(a[mb][3]),
                          "r"(b[nb][0]), "r"(b[nb][1]));
        }
        __syncthreads();
    }

    int rbase = mt*128 + wm*32 + (lane >> 2);
    int cbase = nt*128 + wn*64 + (lane & 3)*2;
    #pragma unroll
    for (int mb = 0; mb < 2; mb++) {
        #pragma unroll
        for (int nb = 0; nb < 8; nb++) {
            int col = cbase + nb*8;
            float bv0 = 0.0f, bv1 = 0.0f;
            if (bias) { bv0 = bias[col]; bv1 = bias[col+1]; }
            float v0 = acc[mb][nb][0] + bv0, v1 = acc[mb][nb][1] + bv1;
            float v2 = acc[mb][nb][2] + bv0, v3 = acc[mb][nb][3] + bv1;
            if (act) { v0 = silu_f(v0); v1 = silu_f(v1); v2 = silu_f(v2); v3 = silu_f(v3); }
            int r0 = rbase + mb*16;
            *(float2*)&C[(size_t)r0*ldc + col]     = make_float2(v0, v1);
            *(float2*)&C[(size_t)(r0+8)*ldc + col] = make_float2(v2, v3);
        }
    }
}

__global__ void __launch_bounds__(256, 2) gemm_mma(
    const __nv_bfloat16* __restrict__ Aop, const __nv_bfloat16* __restrict__ Bop,
    float* __restrict__ C, int ldc, const float* __restrict__ bias, int act)
{
    gemm_body(Aop, Bop, C, ldc, bias, act, blockIdx.x, blockIdx.y);
}

// ---------------- multi-job GEMM: 4 independent GEMMs, one launch --------------
struct GemmJobs {
    const __nv_bfloat16* A[4];
    const __nv_bfloat16* B[4];
    float* C[4];
    const float* bias[4];
    int ldc[4];
    int act[4];
    int ntiles[4];
    int base[4];
};

__global__ void __launch_bounds__(256, 2) gemm_mma_multi(GemmJobs jobs) {
    int bid = blockIdx.x;
    int ji = 0;
    #pragma unroll
    for (int j = 1; j < 4; j++) if (bid >= jobs.base[j]) ji = j;
    int local = bid - jobs.base[ji];
    int nt = local % jobs.ntiles[ji];
    int mt = local / jobs.ntiles[ji];
    gemm_body(jobs.A[ji], jobs.B[ji], jobs.C[ji], jobs.ldc[ji], jobs.bias[ji],
              jobs.act[ji], nt, mt);
}

// ---------------- LayerNorm (fused bf16 operand write) ------------------------
__global__ void ln_kernel(const float* __restrict__ x,
                          const float* __restrict__ w,
                          const float* __restrict__ b) {
    int n = blockIdx.x;
    int t = threadIdx.x;
    float v = x[n*HSZ + t];
    __shared__ float red[256];
    red[t] = v; __syncthreads();
    for (int s = 128; s > 0; s >>= 1) { if (t < s) red[t] += red[t+s]; __syncthreads(); }
    float mu = red[0] * (1.0f/HSZ);
    __syncthreads();
    float d = v - mu;
    red[t] = d*d; __syncthreads();
    for (int s = 128; s > 0; s >>= 1) { if (t < s) red[t] += red[t+s]; __syncthreads(); }
    float var = red[0] * (1.0f/HSZ);
    float xn = d * rsqrtf(var + 1e-5f) * w[t] + b[t];
    __nv_bfloat16 hi = __float2bfloat16(xn);
    __nv_bfloat16 lo = __float2bfloat16(xn - __bfloat162float(hi));
    __nv_bfloat16* dst = opA_xn + (size_t)n*KP + t;
    dst[0]   = hi;
    dst[256] = lo;
    dst[512] = hi;
}

// ---------------- fused attention (writes bf16 operand directly) --------------
__global__ void __launch_bounds__(256) attn_fused() {
    int b = blockIdx.z, h = blockIdx.y, i0 = blockIdx.x * 32;
    __shared__ float Qs[32][33], Ks[32][33], Vs[32][33], Ss[32][33];
    int tid = threadIdx.x;
    int ti = tid & 31;
    int g  = tid >> 5;

    for (int i = tid; i < 1024; i += 256) {
        int r = i >> 5, c = i & 31;
        Qs[r][c] = g_qkv[(size_t)(b*NSZ + i0 + r)*768 + h*HDSZ + c];
    }
    float acc[4] = {0.0f, 0.0f, 0.0f, 0.0f};

    for (int j0 = 0; j0 < NSZ; j0 += 32) {
        __syncthreads();
        for (int i = tid; i < 1024; i += 256) {
            int r = i >> 5, c = i & 31;
            const float* base = &g_qkv[(size_t)(b*NSZ + j0 + r)*768 + h*HDSZ + c];
            Ks[r][c] = base[256];
            Vs[r][c] = base[512];
        }
        __syncthreads();
        #pragma unroll
        for (int jj = 0; jj < 4; jj++) {
            int j = g*4 + jj;
            float s = 0.0f;
            #pragma unroll
            for (int c = 0; c < HDSZ; c++) s += Qs[ti][c] * Ks[j][c];
            Ss[ti][j] = silu_f(s * 0.1767766952966369f);
        }
        __syncthreads();
        #pragma unroll 8
        for (int j = 0; j < 32; j++) {
            float sv = Ss[ti][j];
            #pragma unroll
            for (int dd = 0; dd < 4; dd++) acc[dd] += sv * Vs[j][g*4 + dd];
        }
    }
    union { __nv_bfloat16 h[2]; uint32_t u; } hp0, hp1, lp0, lp1;
    #pragma unroll
    for (int dd = 0; dd < 4; dd++) {
        float v = acc[dd] * (1.0f/NSZ);
        __nv_bfloat16 hi = __float2bfloat16(v);
        __nv_bfloat16 lo = __float2bfloat16(v - __bfloat162float(hi));
        if (dd < 2) { hp0.h[dd] = hi; lp0.h[dd] = lo; }
        else        { hp1.h[dd-2] = hi; lp1.h[dd-2] = lo; }
    }
    size_t ro = (size_t)(b*NSZ + i0 + ti)*KP + h*HDSZ + g*4;
    *(uint32_t*)&opA_vatt[ro]           = hp0.u;
    *(uint32_t*)&opA_vatt[ro + 2]       = hp1.u;
    *(uint32_t*)&opA_vatt[ro + 256]     = lp0.u;
    *(uint32_t*)&opA_vatt[ro + 258]     = lp1.u;
    *(uint32_t*)&opA_vatt[ro + 512]     = hp0.u;
    *(uint32_t*)&opA_vatt[ro + 514]     = hp1.u;
}

// ---------------- edge-wise / elementwise -------------------------------------
__global__ void concat_bias_kernel(const float* __restrict__ a, const float* __restrict__ b) {
    int i = blockIdx.x*256 + threadIdx.x;
    if (i < 256) g_b_dvfw[i] = a[i];
    else if (i < 512) g_b_dvfw[i] = b[i - 256];
}

__global__ void vjconv_kernel(const int* __restrict__ ei, const float* __restrict__ r_ij) {
    int kt = blockIdx.x, et = blockIdx.y;
    int seg = kt >> 2;
    bool lo = (seg == 1);
    int kc = (kt & 3) * 64;
    for (int i = threadIdx.x; i < 1024; i += 256) {
        int r = i >> 3, u = i & 7;
        int e = et*128 + r;
        int s = ei[e];
        float rr = r_ij[e];
        float cv = (rr < 5.0f) ? 0.5f * (cosf(3.14159265358979323846f * rr / 5.0f) + 1.0f) : 0.0f;
        const float* vp = &g_vao[(size_t)s*HSZ + kc + u*8];
        const float* dp = &g_dvfw[(size_t)e*512 + kc + u*8];
        float4 a0 = *(const float4*)vp,       a1 = *(const float4*)(vp + 4);
        float4 b0 = *(const float4*)dp,       b1 = *(const float4*)(dp + 4);
        float f[8] = {a0.x*cv*b0.x, a0.y*cv*b0.y, a0.z*cv*b0.z, a0.w*cv*b0.w,
                      a1.x*cv*b1.x, a1.y*cv*b1.y, a1.z*cv*b1.z, a1.w*cv*b1.w};
        union { __nv_bfloat16 h[8]; uint4 u4; } o;
        #pragma unroll
        for (int j = 0; j < 8; j++) {
            __nv_bfloat16 hi = __float2bfloat16(f[j]);
            o.h[j] = lo ? __float2bfloat16(f[j] - __bfloat162float(hi)) : hi;
        }
        *(uint4*)(opA_vj + (size_t)e*KP + seg*256 + kc + u*8) = o.u4;
        if (seg == 0) {
            float* vj = &g_vj[(size_t)e*HSZ + kc + u*8];
            *(float4*)vj       = make_float4(f[0], f[1], f[2], f[3]);
            *(float4*)(vj + 4) = make_float4(f[4], f[5], f[6], f[7]);
        }
    }
}

__global__ void scatter_kernel(const int* __restrict__ ei,
                               const float* __restrict__ vecin,
                               const float* __restrict__ dij,
                               float* __restrict__ dvec_out) {
    int e = blockIdx.x;
    int h = threadIdx.x;
    int s = ei[e];
    int t = ei[ESZ + e];
    float s1 = g_s12[(size_t)e*512 + h];
    float s2 = g_s12[(size_t)e*512 + 256 + h];
    atomicAdd(&g_xagg[t*HSZ + h], g_vj[e*HSZ + h]);
    #pragma unroll
    for (int d = 0; d < VDSZ; d++) {
        float val = vecin[(size_t)(s*VDSZ + d)*HSZ + h] * s1 + s2 * dij[e*VDSZ + d];
        atomicAdd(&dvec_out[(size_t)(t*VDSZ + d)*HSZ + h], val);
    }
}

__global__ void vecsum_kernel(const float* __restrict__ vecin) {
    int idx = blockIdx.x*256 + threadIdx.x;
    int n = idx >> 8, h = idx & 255;
    float a = 0.0f;
    #pragma unroll
    for (int d = 0; d < VDSZ; d++) a += vecin[(size_t)(n*VDSZ + d)*HSZ + h];
    __nv_bfloat16 hi = __float2bfloat16(a);
    __nv_bfloat16 lo = __float2bfloat16(a - __bfloat162float(hi));
    __nv_bfloat16* dst = opA_vsVD + (size_t)n*KP + h;
    dst[0]   = hi;
    dst[256] = lo;
    dst[512] = hi;
}

__global__ void dx_kernel(float* __restrict__ out_dx) {
    int idx = blockIdx.x*256 + threadIdx.x;
    int n = idx >> 8, h = idx & 255;
    out_dx[idx] = g_vecsum[idx] * g_o[(size_t)n*768 + 256 + h] + g_o[(size_t)n*768 + 512 + h];
}

__global__ void dvec_final_kernel(float* __restrict__ dvec_out) {
    int idx = blockIdx.x*256 + threadIdx.x;
    int n = idx >> 11;
    int d = (idx >> 8) & 7;
    int h = idx & 255;
    dvec_out[idx] += g_v3ts[(size_t)(n*VDSZ + d)*768 + h] * g_o[(size_t)n*768 + h];
}

__global__ void wdot_kernel(const int* __restrict__ ei,
                            const float* __restrict__ dij,
                            float* __restrict__ df_out) {
    int e = blockIdx.x;
    int h = threadIdx.x;
    int s = ei[e];
    int t = ei[ESZ + e];
    float p1 = 0.0f, p2 = 0.0f, ab = 0.0f, s2n = 0.0f;
    #pragma unroll
    for (int d = 0; d < VDSZ; d++) {
        float dd = dij[e*VDSZ + d];
        float a = g_v3ts[(size_t)(t*VDSZ + d)*768 + 256 + h];
        float b = g_v3ts[(size_t)(s*VDSZ + d)*768 + 512 + h];
        ab  += a*b;
        p1  += a*dd;
        p2  += b*dd;
        s2n += dd*dd;
    }
    float wdot = ab - p1*p2*(2.0f - s2n);
    df_out[(size_t)e*HSZ + h] = g_dvfw[(size_t)e*512 + 256 + h] * wdot;
}

// ---------------- host launcher ----------------------------------------------
extern "C" void kernel_launch(void* const* d_in, const int* in_sizes, int n_in,
                              void* d_out, int out_size) {
    const float* x    = (const float*)d_in[0];
    const float* vec  = (const float*)d_in[1];
    const int*   ei   = (const int*)  d_in[2];
    const float* r_ij = (const float*)d_in[3];
    const float* f_ij = (const float*)d_in[4];
    const float* d_ij = (const float*)d_in[5];
    const float* ln_w = (const float*)d_in[7];
    const float* ln_b = (const float*)d_in[8];
    const float* Wq   = (const float*)d_in[9];
    const float* Wk   = (const float*)d_in[10];
    const float* Wv   = (const float*)d_in[11];
    const float* Wao  = (const float*)d_in[12];
    const float* Wvec = (const float*)d_in[13];
    const float* Wdv  = (const float*)d_in[14];
    const float* bdv  = (const float*)d_in[15];
    const float* Ws   = (const float*)d_in[16];
    const float* bs   = (const float*)d_in[17];
    const float* Wo   = (const float*)d_in[18];
    const float* bo   = (const float*)d_in[19];
    const float* Wf   = (const float*)d_in[20];
    const float* bf   = (const float*)d_in[21];
    const float* Wsrc = (const float*)d_in[22];
    const float* Wtrg = (const float*)d_in[23];

    float* out      = (float*)d_out;
    float* out_dx   = out;
    float* out_dvec = out + BNN*HSZ;
    float* out_df   = out + BNN*HSZ + BNN*VDSZ*HSZ;

    float *p_qkv, *p_vao, *p_dvfw, *p_vsum, *p_v3ts, *p_s12, *p_xagg, *p_o, *p_bdvfw;
    cudaGetSymbolAddress((void**)&p_qkv,  g_qkv);
    cudaGetSymbolAddress((void**)&p_vao,  g_vao);
    cudaGetSymbolAddress((void**)&p_dvfw, g_dvfw);
    cudaGetSymbolAddress((void**)&p_vsum, g_vecsum);
    cudaGetSymbolAddress((void**)&p_v3ts, g_v3ts);
    cudaGetSymbolAddress((void**)&p_s12,  g_s12);
    cudaGetSymbolAddress((void**)&p_xagg, g_xagg);
    cudaGetSymbolAddress((void**)&p_o,    g_o);
    cudaGetSymbolAddress((void**)&p_bdvfw, g_b_dvfw);

    __nv_bfloat16 *pA_xn, *pA_vatt, *pA_vsVD, *pA_xagg, *pA_fij, *pA_vec, *pA_vj;
    __nv_bfloat16 *pB_qkv, *pB_Wao, *pB_dvfw, *pB_Wv1, *pB_v3ts, *pB_Ws, *pB_Wo;
    cudaGetSymbolAddress((void**)&pA_xn,   opA_xn);
    cudaGetSymbolAddress((void**)&pA_vatt, opA_vatt);
    cudaGetSymbolAddress((void**)&pA_vsVD, opA_vsVD);
    cudaGetSymbolAddress((void**)&pA_xagg, opA_xagg);
    cudaGetSymbolAddress((void**)&pA_fij,  opA_fij);
    cudaGetSymbolAddress((void**)&pA_vec,  opA_vec);
    cudaGetSymbolAddress((void**)&pA_vj,   opA_vj);
    cudaGetSymbolAddress((void**)&pB_qkv,  opB_qkv);
    cudaGetSymbolAddress((void**)&pB_Wao,  opB_Wao);
    cudaGetSymbolAddress((void**)&pB_dvfw, opB_dvfw);
    cudaGetSymbolAddress((void**)&pB_Wv1,  opB_Wv1);
    cudaGetSymbolAddress((void**)&pB_v3ts, opB_v3ts);
    cudaGetSymbolAddress((void**)&pB_Ws,   opB_Ws);
    cudaGetSymbolAddress((void**)&pB_Wo,   opB_Wo);

    cudaFuncSetAttribute(gemm_mma, cudaFuncAttributeMaxDynamicSharedMemorySize, GEMM_SMEM);
    cudaFuncSetAttribute(gemm_mma_multi, cudaFuncAttributeMaxDynamicSharedMemorySize, GEMM_SMEM);

    // ---- independent producer glue ----
    conv_weights<<<240, 256>>>(Wq, Wk, Wv, Wao, Wdv, Wf, Wvec, Wtrg, Wsrc, Ws, Wo,
                               pB_qkv, pB_Wao, pB_dvfw, pB_Wv1, pB_v3ts, pB_Ws, pB_Wo);
    concat_bias_kernel<<<2,256>>>(bdv, bf);
    ln_kernel<<<BNN,256>>>(x, ln_w, ln_b);
    convA_kernel<<<dim3(12,128),256>>>(f_ij, pA_fij);
    vecsum_kernel<<<BNN*HSZ/256,256>>>(vec);
    convA_kernel<<<dim3(12,128),256>>>(vec, pA_vec);

    // ---- mega-GEMM: v3ts(768) + dvfw(512) + qkv(96) + Wv1(32) in ONE launch ----
    {
        GemmJobs jobs;
        jobs.A[0] = pA_vec;  jobs.B[0] = pB_v3ts; jobs.C[0] = p_v3ts; jobs.bias[0] = nullptr;
        jobs.ldc[0] = 768;   jobs.act[0] = 0;     jobs.ntiles[0] = 6; jobs.base[0] = 0;
        jobs.A[1] = pA_fij;  jobs.B[1] = pB_dvfw; jobs.C[1] = p_dvfw; jobs.bias[1] = p_bdvfw;
        jobs.ldc[1] = 512;   jobs.act[1] = 1;     jobs.ntiles[1] = 4; jobs.base[1] = 768;
        jobs.A[2] = pA_xn;   jobs.B[2] = pB_qkv;  jobs.C[2] = p_qkv;  jobs.bias[2] = nullptr;
        jobs.ldc[2] = 768;   jobs.act[2] = 0;     jobs.ntiles[2] = 6; jobs.base[2] = 1280;
        jobs.A[3] = pA_vsVD; jobs.B[3] = pB_Wv1;  jobs.C[3] = p_vsum; jobs.bias[3] = nullptr;
        jobs.ldc[3] = 256;   jobs.act[3] = 0;     jobs.ntiles[3] = 2; jobs.base[3] = 1376;
        gemm_mma_multi<<<1408, 256, GEMM_SMEM>>>(jobs);
    }

    // ---- attention + Wao ----
    attn_fused<<<dim3(NSZ/32, NHSZ, BSZ),256>>>();
    gemm_mma<<<dim3(2,16),256,GEMM_SMEM>>>(pA_vatt, pB_Wao, p_vao, 256, nullptr, 0);

    // ---- edge pipeline tail ----
    vjconv_kernel<<<dim3(12,128),256>>>(ei, r_ij);
    gemm_mma<<<dim3(4,128),256,GEMM_SMEM>>>(pA_vj, pB_Ws, p_s12, 512, bs, 1);

    cudaMemsetAsync(p_xagg, 0, (size_t)BNN*HSZ*sizeof(float));
    cudaMemsetAsync(out_dvec, 0, (size_t)BNN*VDSZ*HSZ*sizeof(float));
    scatter_kernel<<<ESZ,256>>>(ei, vec, d_ij, out_dvec);

    convA_kernel<<<dim3(12,16),256>>>(p_xagg, pA_xagg);
    gemm_mma<<<dim3(6,16),256,GEMM_SMEM>>>(pA_xagg, pB_Wo, p_o, 768, bo, 0);

    dx_kernel<<<BNN*HSZ/256,256>>>(out_dx);
    dvec_final_kernel<<<BNN*VDSZ*HSZ/256,256>>>(out_dvec);
    wdot_kernel<<<ESZ,256>>>(ei, d_ij, out_df);
}

// round 11
// speedup vs baseline: 1.8889x; 1.0086x over previous
#include <cuda_runtime.h>
#include <cuda_bf16.h>
#include <cstdint>
#include <math.h>

#define BNN 2048
#define HSZ 256
#define ESZ 16384
#define BSZ 8
#define NSZ 256
#define NHSZ 8
#define HDSZ 32
#define VDSZ 8

#define KP 768                    // K' = 3*256 bf16 cols
#define KP_BYTES 1536

// ---------------- fp32 scratch ------------------------------------------------
__device__ float g_qkv[BNN*3*HSZ];
__device__ float g_vao[BNN*HSZ];
__device__ float g_dvfw[ESZ*2*HSZ];          // [dv | fw] (both silu'd)
__device__ float g_vecsum[BNN*HSZ];
__device__ float g_v3ts[ESZ*3*HSZ];          // [vec3 | vt | vs] (rows = BNN*VD)
__device__ float g_s12[ESZ*2*HSZ];
__device__ float g_xagg[BNN*HSZ];
__device__ float g_o[BNN*3*HSZ];
__device__ float g_b_dvfw[2*HSZ];

// ---------------- bf16 operand scratch (row-major [rows][768]) ----------------
__device__ __nv_bfloat16 opA_xn  [BNN*KP];
__device__ __nv_bfloat16 opA_vatt[BNN*KP];
__device__ __nv_bfloat16 opA_vsVD[BNN*KP];
__device__ __nv_bfloat16 opA_xagg[BNN*KP];
__device__ __nv_bfloat16 opA_fij [ESZ*KP];
__device__ __nv_bfloat16 opA_vec [ESZ*KP];
__device__ __nv_bfloat16 opA_vj  [ESZ*KP];
__device__ __nv_bfloat16 opB_qkv [768*KP];
__device__ __nv_bfloat16 opB_Wao [256*KP];
__device__ __nv_bfloat16 opB_dvfw[512*KP];
__device__ __nv_bfloat16 opB_Wv1 [256*KP];
__device__ __nv_bfloat16 opB_v3ts[768*KP];
__device__ __nv_bfloat16 opB_Ws  [512*KP];
__device__ __nv_bfloat16 opB_Wo  [768*KP];

__device__ __forceinline__ float silu_f(float x) { return x / (1.0f + __expf(-x)); }

// ---------------- operand conversion A (fp32 -> bf16 hi/lo, row-major) --------
__global__ void convA_kernel(const float* __restrict__ A, __nv_bfloat16* __restrict__ dst) {
    int kt = blockIdx.x, mt = blockIdx.y;
    bool lo = ((kt >> 2) == 1);
    int seg = kt >> 2;
    int kc = (kt & 3) * 64;
    for (int i = threadIdx.x; i < 1024; i += 256) {
        int r = i >> 3, u = i & 7;
        const float* src = A + (size_t)(mt*128 + r)*HSZ + kc + u*8;
        float4 f0 = *(const float4*)src;
        float4 f1 = *(const float4*)(src + 4);
        float f[8] = {f0.x, f0.y, f0.z, f0.w, f1.x, f1.y, f1.z, f1.w};
        union { __nv_bfloat16 h[8]; uint4 u4; } o;
        #pragma unroll
        for (int j = 0; j < 8; j++) {
            __nv_bfloat16 hi = __float2bfloat16(f[j]);
            o.h[j] = lo ? __float2bfloat16(f[j] - __bfloat162float(hi)) : hi;
        }
        *(uint4*)(dst + (size_t)(mt*128 + r)*KP + seg*256 + kc + u*8) = o.u4;
    }
}

// ---------------- fused weight conversion (coalesced, 12 jobs) ----------------
__global__ void __launch_bounds__(256) conv_weights(
    const float* __restrict__ Wq, const float* __restrict__ Wk, const float* __restrict__ Wv,
    const float* __restrict__ Wao, const float* __restrict__ Wdv, const float* __restrict__ Wf,
    const float* __restrict__ Wvec, const float* __restrict__ Wtrg, const float* __restrict__ Wsrc,
    const float* __restrict__ Ws, const float* __restrict__ Wo,
    __nv_bfloat16* __restrict__ dq, __nv_bfloat16* __restrict__ dao,
    __nv_bfloat16* __restrict__ ddvfw, __nv_bfloat16* __restrict__ dwv1,
    __nv_bfloat16* __restrict__ dv3ts, __nv_bfloat16* __restrict__ dws,
    __nv_bfloat16* __restrict__ dwo)
{
    int t = blockIdx.x;
    const float* src; __nv_bfloat16* dst; int ldb, colOff, ntn, local;
    if (t < 160) {
        int j = t >> 4; local = t & 15; ntn = 4;
        switch (j) {
            case 0: src = Wq;   dst = dq;                       ldb = 256; colOff = 0;   break;
            case 1: src = Wk;   dst = dq + (size_t)256*KP;      ldb = 256; colOff = 0;   break;
            case 2: src = Wv;   dst = dq + (size_t)512*KP;      ldb = 256; colOff = 0;   break;
            case 3: src = Wao;  dst = dao;                      ldb = 256; colOff = 0;   break;
            case 4: src = Wdv;  dst = ddvfw;                    ldb = 256; colOff = 0;   break;
            case 5: src = Wf;   dst = ddvfw + (size_t)256*KP;   ldb = 256; colOff = 0;   break;
            case 6: src = Wvec; dst = dwv1;                     ldb = 512; colOff = 0;   break;
            case 7: src = Wvec; dst = dv3ts;                    ldb = 512; colOff = 256; break;
            case 8: src = Wtrg; dst = dv3ts + (size_t)256*KP;   ldb = 256; colOff = 0;   break;
            default:src = Wsrc; dst = dv3ts + (size_t)512*KP;   ldb = 256; colOff = 0;   break;
        }
    } else if (t < 192) {
        local = t - 160; ntn = 8;
        src = Ws; dst = dws; ldb = 512; colOff = 0;
    } else {
        local = t - 192; ntn = 12;
        src = Wo; dst = dwo; ldb = 768; colOff = 0;
    }
    int nt = local % ntn;
    int kt = local / ntn;
    int base_k = kt * 64;
    int base_n = colOff + nt * 64;

    __shared__ float Wt[64][65];
    int tid = threadIdx.x;
    for (int i = tid; i < 4096; i += 256) {
        int r = i >> 6, c = i & 63;
        Wt[r][c] = src[(size_t)(base_k + r)*ldb + base_n + c];
    }
    __syncthreads();
    for (int i = tid; i < 2048; i += 256) {
        int c = i >> 5;
        int k2 = (i & 31) * 2;
        float v0 = Wt[k2][c], v1 = Wt[k2+1][c];
        __nv_bfloat16 h0 = __float2bfloat16(v0), h1 = __float2bfloat16(v1);
        __nv_bfloat16 l0 = __float2bfloat16(v0 - __bfloat162float(h0));
        __nv_bfloat16 l1 = __float2bfloat16(v1 - __bfloat162float(h1));
        union { __nv_bfloat16 h[2]; uint32_t u; } hp, lp;
        hp.h[0] = h0; hp.h[1] = h1; lp.h[0] = l0; lp.h[1] = l1;
        size_t ro = (size_t)(nt*64 + c)*KP + kt*64 + k2;
        *(uint32_t*)&dst[ro]       = hp.u;
        *(uint32_t*)&dst[ro + 256] = hp.u;
        *(uint32_t*)&dst[ro + 512] = lp.u;
    }
}

// ---------------- mma.sync bf16x3 GEMM core (BK=64) ---------------------------
#define SPITCH 144
#define STILE (128*SPITCH)
#define SSTAGE (2*STILE)
#define GEMM_SMEM (2*SSTAGE)

__device__ __forceinline__ uint32_t smem_u32(const void* p) {
    uint32_t a;
    asm("{ .reg .u64 t; cvta.to.shared.u64 t, %1; cvt.u32.u64 %0, t; }" : "=r"(a) : "l"(p));
    return a;
}

__device__ __forceinline__ void gemm_body(
    const __nv_bfloat16* __restrict__ Aop, const __nv_bfloat16* __restrict__ Bop,
    float* __restrict__ C, int ldc, const float* __restrict__ bias, int act,
    int nt, int mt)
{
    extern __shared__ __align__(16) char smem[];
    int tid = threadIdx.x;
    int lane = tid & 31, wid = tid >> 5;
    int wm = wid & 3, wn = wid >> 2;
    const char* gA = (const char*)Aop + (size_t)mt*128*KP_BYTES;
    const char* gB = (const char*)Bop + (size_t)nt*128*KP_BYTES;
    uint32_t sbase = smem_u32(smem);

    auto load_stage = [&](int buf, int s) {
        uint32_t dst0 = sbase + buf*SSTAGE;
        #pragma unroll
        for (int t = 0; t < 8; t++) {
            int ci = tid + t*256;
            int isB = ci >> 10;
            int cc = ci & 1023;
            int row = cc >> 3, c = cc & 7;
            uint32_t dst = dst0 + isB*STILE + row*SPITCH + c*16;
            const char* src = (isB ? gB : gA) + (size_t)row*KP_BYTES + s*128 + c*16;
            asm volatile("cp.async.cg.shared.global [%0], [%1], 16;\n" :: "r"(dst), "l"(src));
        }
        asm volatile("cp.async.commit_group;\n");
    };

    float acc[2][8][4];
    #pragma unroll
    for (int i = 0; i < 2; i++)
        #pragma unroll
        for (int j = 0; j < 8; j++)
            #pragma unroll
            for (int k = 0; k < 4; k++) acc[i][j][k] = 0.0f;

    load_stage(0, 0);
    const int NS = KP/64;
    for (int s = 0; s < NS; s++) {
        int buf = s & 1;
        if (s + 1 < NS) {
            load_stage(buf ^ 1, s + 1);
            asm volatile("cp.async.wait_group 1;\n");
        } else {
            asm volatile("cp.async.wait_group 0;\n");
        }
        __syncthreads();
        uint32_t bA = sbase + buf*SSTAGE;
        uint32_t bB = bA + STILE;
        #pragma unroll
        for (int kk = 0; kk < 64; kk += 16) {
            uint32_t a[2][4];
            #pragma unroll
            for (int mb = 0; mb < 2; mb++) {
                uint32_t addr = bA + (wm*32 + mb*16 + (lane & 15))*SPITCH
                                   + (kk + ((lane >> 4) << 3))*2;
                asm volatile("ldmatrix.sync.aligned.m8n8.x4.shared.b16 {%0,%1,%2,%3}, [%4];"
                    : "=r"(a[mb][0]), "=r"(a[mb][1]), "=r"(a[mb][2]), "=r"(a[mb][3]) : "r"(addr));
            }
            uint32_t b[8][2];
            #pragma unroll
            for (int nb4 = 0; nb4 < 4; nb4++) {
                uint32_t r0, r1, r2, r3;
                uint32_t addr = bB + (wn*64 + nb4*16 + (lane & 15))*SPITCH
                                   + (kk + ((lane >> 4) << 3))*2;
                asm volatile("ldmatrix.sync.aligned.m8n8.x4.shared.b16 {%0,%1,%2,%3}, [%4];"
                    : "=r"(r0), "=r"(r1), "=r"(r2), "=r"(r3) : "r"(addr));
                b[nb4*2][0] = r0; b[nb4*2][1] = r2;
                b[nb4*2+1][0] = r1; b[nb4*2+1][1] = r3;
            }
            #pragma unroll
            for (int mb = 0; mb < 2; mb++)
                #pragma unroll
                for (int nb = 0; nb < 8; nb++)
                    asm volatile("mma.sync.aligned.m16n8k16.row.col.f32.bf16.bf16.f32 "
                        "{%0,%1,%2,%3}, {%4,%5,%6,%7}, {%8,%9}, {%0,%1,%2,%3};"
                        : "+f"(acc[mb][nb][0]), "+f"(acc[mb][nb][1]),
                          "+f"(acc[mb][nb][2]), "+f"(acc[mb][nb][3])
                        : "r"(a[mb][0]), "r"(a[mb][1]), "r"(a[mb][2]), "r"(a[mb][3]),
                          "r"(b[nb][0]), "r"(b[nb][1]));
        }
        __syncthreads();
    }

    int rbase = mt*128 + wm*32 + (lane >> 2);
    int cbase = nt*128 + wn*64 + (lane & 3)*2;
    #pragma unroll
    for (int mb = 0; mb < 2; mb++) {
        #pragma unroll
        for (int nb = 0; nb < 8; nb++) {
            int col = cbase + nb*8;
            float bv0 = 0.0f, bv1 = 0.0f;
            if (bias) { bv0 = bias[col]; bv1 = bias[col+1]; }
            float v0 = acc[mb][nb][0] + bv0, v1 = acc[mb][nb][1] + bv1;
            float v2 = acc[mb][nb][2] + bv0, v3 = acc[mb][nb][3] + bv1;
            if (act) { v0 = silu_f(v0); v1 = silu_f(v1); v2 = silu_f(v2); v3 = silu_f(v3); }
            int r0 = rbase + mb*16;
            *(float2*)&C[(size_t)r0*ldc + col]     = make_float2(v0, v1);
            *(float2*)&C[(size_t)(r0+8)*ldc + col] = make_float2(v2, v3);
        }
    }
}

__global__ void __launch_bounds__(256, 2) gemm_mma(
    const __nv_bfloat16* __restrict__ Aop, const __nv_bfloat16* __restrict__ Bop,
    float* __restrict__ C, int ldc, const float* __restrict__ bias, int act)
{
    gemm_body(Aop, Bop, C, ldc, bias, act, blockIdx.x, blockIdx.y);
}

// ---------------- multi-job GEMM -----------------------------------------------
struct GemmJobs {
    const __nv_bfloat16* A[4];
    const __nv_bfloat16* B[4];
    float* C[4];
    const float* bias[4];
    int ldc[4];
    int act[4];
    int ntiles[4];
    int base[4];
};

__global__ void __launch_bounds__(256, 2) gemm_mma_multi(GemmJobs jobs) {
    int bid = blockIdx.x;
    int ji = 0;
    #pragma unroll
    for (int j = 1; j < 4; j++) if (bid >= jobs.base[j]) ji = j;
    int local = bid - jobs.base[ji];
    int nt = local % jobs.ntiles[ji];
    int mt = local / jobs.ntiles[ji];
    gemm_body(jobs.A[ji], jobs.B[ji], jobs.C[ji], jobs.ldc[ji], jobs.bias[ji],
              jobs.act[ji], nt, mt);
}

// ---------------- LayerNorm (fused bf16 operand write) ------------------------
__global__ void ln_kernel(const float* __restrict__ x,
                          const float* __restrict__ w,
                          const float* __restrict__ b) {
    int n = blockIdx.x;
    int t = threadIdx.x;
    float v = x[n*HSZ + t];
    __shared__ float red[256];
    red[t] = v; __syncthreads();
    for (int s = 128; s > 0; s >>= 1) { if (t < s) red[t] += red[t+s]; __syncthreads(); }
    float mu = red[0] * (1.0f/HSZ);
    __syncthreads();
    float d = v - mu;
    red[t] = d*d; __syncthreads();
    for (int s = 128; s > 0; s >>= 1) { if (t < s) red[t] += red[t+s]; __syncthreads(); }
    float var = red[0] * (1.0f/HSZ);
    float xn = d * rsqrtf(var + 1e-5f) * w[t] + b[t];
    __nv_bfloat16 hi = __float2bfloat16(xn);
    __nv_bfloat16 lo = __float2bfloat16(xn - __bfloat162float(hi));
    __nv_bfloat16* dst = opA_xn + (size_t)n*KP + t;
    dst[0]   = hi;
    dst[256] = lo;
    dst[512] = hi;
}

// ---------------- fused attention (writes bf16 operand for Wao GEMM) ----------
__global__ void __launch_bounds__(256) attn_fused() {
    int b = blockIdx.z, h = blockIdx.y, i0 = blockIdx.x * 32;
    __shared__ float Qs[32][33], Ks[32][33], Vs[32][33], Ss[32][33];
    int tid = threadIdx.x;
    int ti = tid & 31;
    int g  = tid >> 5;

    for (int i = tid; i < 1024; i += 256) {
        int r = i >> 5, c = i & 31;
        Qs[r][c] = g_qkv[(size_t)(b*NSZ + i0 + r)*768 + h*HDSZ + c];
    }
    float acc[4] = {0.0f, 0.0f, 0.0f, 0.0f};

    for (int j0 = 0; j0 < NSZ; j0 += 32) {
        __syncthreads();
        for (int i = tid; i < 1024; i += 256) {
            int r = i >> 5, c = i & 31;
            const float* base = &g_qkv[(size_t)(b*NSZ + j0 + r)*768 + h*HDSZ + c];
            Ks[r][c] = base[256];
            Vs[r][c] = base[512];
        }
        __syncthreads();
        #pragma unroll
        for (int jj = 0; jj < 4; jj++) {
            int j = g*4 + jj;
            float s = 0.0f;
            #pragma unroll
            for (int c = 0; c < HDSZ; c++) s += Qs[ti][c] * Ks[j][c];
            Ss[ti][j] = silu_f(s * 0.1767766952966369f);
        }
        __syncthreads();
        #pragma unroll 8
        for (int j = 0; j < 32; j++) {
            float sv = Ss[ti][j];
            #pragma unroll
            for (int dd = 0; dd < 4; dd++) acc[dd] += sv * Vs[j][g*4 + dd];
        }
    }
    union { __nv_bfloat16 h[2]; uint32_t u; } hp0, hp1, lp0, lp1;
    #pragma unroll
    for (int dd = 0; dd < 4; dd++) {
        float v = acc[dd] * (1.0f/NSZ);
        __nv_bfloat16 hi = __float2bfloat16(v);
        __nv_bfloat16 lo = __float2bfloat16(v - __bfloat162float(hi));
        if (dd < 2) { hp0.h[dd] = hi; lp0.h[dd] = lo; }
        else        { hp1.h[dd-2] = hi; lp1.h[dd-2] = lo; }
    }
    size_t ro = (size_t)(b*NSZ + i0 + ti)*KP + h*HDSZ + g*4;
    *(uint32_t*)&opA_vatt[ro]           = hp0.u;
    *(uint32_t*)&opA_vatt[ro + 2]       = hp1.u;
    *(uint32_t*)&opA_vatt[ro + 256]     = lp0.u;
    *(uint32_t*)&opA_vatt[ro + 258]     = lp1.u;
    *(uint32_t*)&opA_vatt[ro + 512]     = hp0.u;
    *(uint32_t*)&opA_vatt[ro + 514]     = hp1.u;
}

// ---------------- edge-wise / elementwise -------------------------------------
__global__ void concat_bias_kernel(const float* __restrict__ a, const float* __restrict__ b) {
    int i = blockIdx.x*256 + threadIdx.x;
    if (i < 256) g_b_dvfw[i] = a[i];
    else if (i < 512) g_b_dvfw[i] = b[i - 256];
}

// fused: cutoff + v_j compute -> bf16 operand; seg0 also does x_agg atomics
__global__ void vjconv_kernel(const int* __restrict__ ei, const float* __restrict__ r_ij) {
    int kt = blockIdx.x, et = blockIdx.y;
    int seg = kt >> 2;
    bool lo = (seg == 1);
    int kc = (kt & 3) * 64;
    for (int i = threadIdx.x; i < 1024; i += 256) {
        int r = i >> 3, u = i & 7;
        int e = et*128 + r;
        int s = ei[e];
        float rr = r_ij[e];
        float cv = (rr < 5.0f) ? 0.5f * (cosf(3.14159265358979323846f * rr / 5.0f) + 1.0f) : 0.0f;
        const float* vp = &g_vao[(size_t)s*HSZ + kc + u*8];
        const float* dp = &g_dvfw[(size_t)e*512 + kc + u*8];
        float4 a0 = *(const float4*)vp,       a1 = *(const float4*)(vp + 4);
        float4 b0 = *(const float4*)dp,       b1 = *(const float4*)(dp + 4);
        float f[8] = {a0.x*cv*b0.x, a0.y*cv*b0.y, a0.z*cv*b0.z, a0.w*cv*b0.w,
                      a1.x*cv*b1.x, a1.y*cv*b1.y, a1.z*cv*b1.z, a1.w*cv*b1.w};
        union { __nv_bfloat16 h[8]; uint4 u4; } o;
        #pragma unroll
        for (int j = 0; j < 8; j++) {
            __nv_bfloat16 hi = __float2bfloat16(f[j]);
            o.h[j] = lo ? __float2bfloat16(f[j] - __bfloat162float(hi)) : hi;
        }
        *(uint4*)(opA_vj + (size_t)e*KP + seg*256 + kc + u*8) = o.u4;
        if (seg == 0) {
            int t2 = ei[ESZ + e];
            float* xa = &g_xagg[(size_t)t2*HSZ + kc + u*8];
            #pragma unroll
            for (int j = 0; j < 8; j++) atomicAdd(xa + j, f[j]);
        }
    }
}

__global__ void scatter_vec_kernel(const int* __restrict__ ei,
                                   const float* __restrict__ vecin,
                                   const float* __restrict__ dij,
                                   float* __restrict__ dvec_out) {
    int e = blockIdx.x;
    int h = threadIdx.x;
    int s = ei[e];
    int t = ei[ESZ + e];
    float s1 = g_s12[(size_t)e*512 + h];
    float s2 = g_s12[(size_t)e*512 + 256 + h];
    #pragma unroll
    for (int d = 0; d < VDSZ; d++) {
        float val = vecin[(size_t)(s*VDSZ + d)*HSZ + h] * s1 + s2 * dij[e*VDSZ + d];
        atomicAdd(&dvec_out[(size_t)(t*VDSZ + d)*HSZ + h], val);
    }
}

__global__ void vecsum_kernel(const float* __restrict__ vecin) {
    int idx = blockIdx.x*256 + threadIdx.x;
    int n = idx >> 8, h = idx & 255;
    float a = 0.0f;
    #pragma unroll
    for (int d = 0; d < VDSZ; d++) a += vecin[(size_t)(n*VDSZ + d)*HSZ + h];
    __nv_bfloat16 hi = __float2bfloat16(a);
    __nv_bfloat16 lo = __float2bfloat16(a - __bfloat162float(hi));
    __nv_bfloat16* dst = opA_vsVD + (size_t)n*KP + h;
    dst[0]   = hi;
    dst[256] = lo;
    dst[512] = hi;
}

__global__ void dx_kernel(float* __restrict__ out_dx) {
    int idx = blockIdx.x*256 + threadIdx.x;
    int n = idx >> 8, h = idx & 255;
    out_dx[idx] = g_vecsum[idx] * g_o[(size_t)n*768 + 256 + h] + g_o[(size_t)n*768 + 512 + h];
}

__global__ void dvec_final_kernel(float* __restrict__ dvec_out) {
    int idx = blockIdx.x*256 + threadIdx.x;
    int n = idx >> 11;
    int d = (idx >> 8) & 7;
    int h = idx & 255;
    dvec_out[idx] += g_v3ts[(size_t)(n*VDSZ + d)*768 + h] * g_o[(size_t)n*768 + h];
}

__global__ void wdot_kernel(const int* __restrict__ ei,
                            const float* __restrict__ dij,
                            float* __restrict__ df_out) {
    int e = blockIdx.x;
    int h = threadIdx.x;
    int s = ei[e];
    int t = ei[ESZ + e];
    float p1 = 0.0f, p2 = 0.0f, ab = 0.0f, s2n = 0.0f;
    #pragma unroll
    for (int d = 0; d < VDSZ; d++) {
        float dd = dij[e*VDSZ + d];
        float a = g_v3ts[(size_t)(t*VDSZ + d)*768 + 256 + h];
        float b = g_v3ts[(size_t)(s*VDSZ + d)*768 + 512 + h];
        ab  += a*b;
        p1  += a*dd;
        p2  += b*dd;
        s2n += dd*dd;
    }
    float wdot = ab - p1*p2*(2.0f - s2n);
    df_out[(size_t)e*HSZ + h] = g_dvfw[(size_t)e*512 + 256 + h] * wdot;
}

// ---------------- host launcher ----------------------------------------------
extern "C" void kernel_launch(void* const* d_in, const int* in_sizes, int n_in,
                              void* d_out, int out_size) {
    const float* x    = (const float*)d_in[0];
    const float* vec  = (const float*)d_in[1];
    const int*   ei   = (const int*)  d_in[2];
    const float* r_ij = (const float*)d_in[3];
    const float* f_ij = (const float*)d_in[4];
    const float* d_ij = (const float*)d_in[5];
    const float* ln_w = (const float*)d_in[7];
    const float* ln_b = (const float*)d_in[8];
    const float* Wq   = (const float*)d_in[9];
    const float* Wk   = (const float*)d_in[10];
    const float* Wv   = (const float*)d_in[11];
    const float* Wao  = (const float*)d_in[12];
    const float* Wvec = (const float*)d_in[13];
    const float* Wdv  = (const float*)d_in[14];
    const float* bdv  = (const float*)d_in[15];
    const float* Ws   = (const float*)d_in[16];
    const float* bs   = (const float*)d_in[17];
    const float* Wo   = (const float*)d_in[18];
    const float* bo   = (const float*)d_in[19];
    const float* Wf   = (const float*)d_in[20];
    const float* bf   = (const float*)d_in[21];
    const float* Wsrc = (const float*)d_in[22];
    const float* Wtrg = (const float*)d_in[23];

    float* out      = (float*)d_out;
    float* out_dx   = out;
    float* out_dvec = out + BNN*HSZ;
    float* out_df   = out + BNN*HSZ + BNN*VDSZ*HSZ;

    float *p_qkv, *p_vao, *p_dvfw, *p_vsum, *p_v3ts, *p_s12, *p_xagg, *p_o, *p_bdvfw;
    cudaGetSymbolAddress((void**)&p_qkv,  g_qkv);
    cudaGetSymbolAddress((void**)&p_vao,  g_vao);
    cudaGetSymbolAddress((void**)&p_dvfw, g_dvfw);
    cudaGetSymbolAddress((void**)&p_vsum, g_vecsum);
    cudaGetSymbolAddress((void**)&p_v3ts, g_v3ts);
    cudaGetSymbolAddress((void**)&p_s12,  g_s12);
    cudaGetSymbolAddress((void**)&p_xagg, g_xagg);
    cudaGetSymbolAddress((void**)&p_o,    g_o);
    cudaGetSymbolAddress((void**)&p_bdvfw, g_b_dvfw);

    __nv_bfloat16 *pA_xn, *pA_vatt, *pA_vsVD, *pA_xagg, *pA_fij, *pA_vec, *pA_vj;
    __nv_bfloat16 *pB_qkv, *pB_Wao, *pB_dvfw, *pB_Wv1, *pB_v3ts, *pB_Ws, *pB_Wo;
    cudaGetSymbolAddress((void**)&pA_xn,   opA_xn);
    cudaGetSymbolAddress((void**)&pA_vatt, opA_vatt);
    cudaGetSymbolAddress((void**)&pA_vsVD, opA_vsVD);
    cudaGetSymbolAddress((void**)&pA_xagg, opA_xagg);
    cudaGetSymbolAddress((void**)&pA_fij,  opA_fij);
    cudaGetSymbolAddress((void**)&pA_vec,  opA_vec);
    cudaGetSymbolAddress((void**)&pA_vj,   opA_vj);
    cudaGetSymbolAddress((void**)&pB_qkv,  opB_qkv);
    cudaGetSymbolAddress((void**)&pB_Wao,  opB_Wao);
    cudaGetSymbolAddress((void**)&pB_dvfw, opB_dvfw);
    cudaGetSymbolAddress((void**)&pB_Wv1,  opB_Wv1);
    cudaGetSymbolAddress((void**)&pB_v3ts, opB_v3ts);
    cudaGetSymbolAddress((void**)&pB_Ws,   opB_Ws);
    cudaGetSymbolAddress((void**)&pB_Wo,   opB_Wo);

    cudaFuncSetAttribute(gemm_mma, cudaFuncAttributeMaxDynamicSharedMemorySize, GEMM_SMEM);
    cudaFuncSetAttribute(gemm_mma_multi, cudaFuncAttributeMaxDynamicSharedMemorySize, GEMM_SMEM);

    // ---- early memsets (hidden before mega-GEMM) ----
    cudaMemsetAsync(p_xagg, 0, (size_t)BNN*HSZ*sizeof(float));
    cudaMemsetAsync(out_dvec, 0, (size_t)BNN*VDSZ*HSZ*sizeof(float));

    // ---- independent producer glue ----
    conv_weights<<<240, 256>>>(Wq, Wk, Wv, Wao, Wdv, Wf, Wvec, Wtrg, Wsrc, Ws, Wo,
                               pB_qkv, pB_Wao, pB_dvfw, pB_Wv1, pB_v3ts, pB_Ws, pB_Wo);
    concat_bias_kernel<<<2,256>>>(bdv, bf);
    ln_kernel<<<BNN,256>>>(x, ln_w, ln_b);
    convA_kernel<<<dim3(12,128),256>>>(f_ij, pA_fij);
    vecsum_kernel<<<BNN*HSZ/256,256>>>(vec);
    convA_kernel<<<dim3(12,128),256>>>(vec, pA_vec);

    // ---- mega-GEMM 1: v3ts + dvfw + qkv + Wv1 ----
    {
        GemmJobs jobs;
        jobs.A[0] = pA_vec;  jobs.B[0] = pB_v3ts; jobs.C[0] = p_v3ts; jobs.bias[0] = nullptr;
        jobs.ldc[0] = 768;   jobs.act[0] = 0;     jobs.ntiles[0] = 6; jobs.base[0] = 0;
        jobs.A[1] = pA_fij;  jobs.B[1] = pB_dvfw; jobs.C[1] = p_dvfw; jobs.bias[1] = p_bdvfw;
        jobs.ldc[1] = 512;   jobs.act[1] = 1;     jobs.ntiles[1] = 4; jobs.base[1] = 768;
        jobs.A[2] = pA_xn;   jobs.B[2] = pB_qkv;  jobs.C[2] = p_qkv;  jobs.bias[2] = nullptr;
        jobs.ldc[2] = 768;   jobs.act[2] = 0;     jobs.ntiles[2] = 6; jobs.base[2] = 1280;
        jobs.A[3] = pA_vsVD; jobs.B[3] = pB_Wv1;  jobs.C[3] = p_vsum; jobs.bias[3] = nullptr;
        jobs.ldc[3] = 256;   jobs.act[3] = 0;     jobs.ntiles[3] = 2; jobs.base[3] = 1376;
        gemm_mma_multi<<<1408, 256, GEMM_SMEM>>>(jobs);
    }

    // ---- attention + Wao GEMM (per-head attention; Wao must stay separate) ----
    attn_fused<<<dim3(NSZ/32, NHSZ, BSZ),256>>>();
    gemm_mma<<<dim3(2,16),256,GEMM_SMEM>>>(pA_vatt, pB_Wao, p_vao, 256, nullptr, 0);

    // ---- edge tail: vjconv (+x_agg atomics) -> convA_xagg -> {Ws, Wo} batch ----
    vjconv_kernel<<<dim3(12,128),256>>>(ei, r_ij);
    convA_kernel<<<dim3(12,16),256>>>(p_xagg, pA_xagg);
    {
        GemmJobs jobs;
        jobs.A[0] = pA_vj;   jobs.B[0] = pB_Ws; jobs.C[0] = p_s12; jobs.bias[0] = bs;
        jobs.ldc[0] = 512;   jobs.act[0] = 1;   jobs.ntiles[0] = 4; jobs.base[0] = 0;
        jobs.A[1] = pA_xagg; jobs.B[1] = pB_Wo; jobs.C[1] = p_o;   jobs.bias[1] = bo;
        jobs.ldc[1] = 768;   jobs.act[1] = 0;   jobs.ntiles[1] = 6; jobs.base[1] = 512;
        jobs.A[2] = jobs.A[0]; jobs.B[2] = jobs.B[0]; jobs.C[2] = jobs.C[0]; jobs.bias[2] = nullptr;
        jobs.ldc[2] = 512; jobs.act[2] = 0; jobs.ntiles[2] = 1; jobs.base[2] = 1 << 30;
        jobs.A[3] = jobs.A[0]; jobs.B[3] = jobs.B[0]; jobs.C[3] = jobs.C[0]; jobs.bias[3] = nullptr;
        jobs.ldc[3] = 512; jobs.act[3] = 0; jobs.ntiles[3] = 1; jobs.base[3] = 1 << 30;
        gemm_mma_multi<<<608, 256, GEMM_SMEM>>>(jobs);
    }

    // ---- finals ----
    scatter_vec_kernel<<<ESZ,256>>>(ei, vec, d_ij, out_dvec);
    dx_kernel<<<BNN*HSZ/256,256>>>(out_dx);
    dvec_final_kernel<<<BNN*VDSZ*HSZ/256,256>>>(out_dvec);
    wdot_kernel<<<ESZ,256>>>(ei, d_ij, out_df);
}

// round 15
// speedup vs baseline: 1.9087x; 1.0105x over previous
#include <cuda_runtime.h>
#include <cuda_bf16.h>
#include <cstdint>
#include <math.h>

#define BNN 2048
#define HSZ 256
#define ESZ 16384
#define BSZ 8
#define NSZ 256
#define NHSZ 8
#define HDSZ 32
#define VDSZ 8

#define KP 512                    // stored operand width: [hi | lo] bf16
#define KP_BYTES 1024
#define NSCH 12                   // logical K' chunks of 64 (hi*hi, lo*hi, hi*lo)

// ---------------- fp32 scratch ------------------------------------------------
__device__ float g_qkv[BNN*3*HSZ];
__device__ float g_vao[BNN*HSZ];
__device__ float g_dvfw[ESZ*2*HSZ];          // [dv | fw] (both silu'd)
__device__ float g_vecsum[BNN*HSZ];
__device__ float g_v3ts[ESZ*3*HSZ];          // [vec3 | vt | vs] (rows = BNN*VD)
__device__ float g_s12[ESZ*2*HSZ];
__device__ float g_xagg[BNN*HSZ];
__device__ float g_o[BNN*3*HSZ];
__device__ float g_b_dvfw[2*HSZ];

// ---------------- bf16 operand scratch (row-major [rows][512] = [hi|lo]) ------
__device__ __nv_bfloat16 opA_xn  [BNN*KP];
__device__ __nv_bfloat16 opA_vatt[BNN*KP];
__device__ __nv_bfloat16 opA_vsVD[BNN*KP];
__device__ __nv_bfloat16 opA_xagg[BNN*KP];
__device__ __nv_bfloat16 opA_fij [ESZ*KP];
__device__ __nv_bfloat16 opA_vec [ESZ*KP];
__device__ __nv_bfloat16 opA_vj  [ESZ*KP];
__device__ __nv_bfloat16 opB_qkv [768*KP];
__device__ __nv_bfloat16 opB_Wao [256*KP];
__device__ __nv_bfloat16 opB_dvfw[512*KP];
__device__ __nv_bfloat16 opB_Wv1 [256*KP];
__device__ __nv_bfloat16 opB_v3ts[768*KP];
__device__ __nv_bfloat16 opB_Ws  [512*KP];
__device__ __nv_bfloat16 opB_Wo  [768*KP];

__device__ __forceinline__ float silu_f(float x) { return x / (1.0f + __expf(-x)); }

// ---------------- operand conversion A (fp32 -> bf16 [hi|lo]) -----------------
__global__ void convA_kernel(const float* __restrict__ A, __nv_bfloat16* __restrict__ dst) {
    int kt = blockIdx.x, mt = blockIdx.y;     // kt 0..7
    bool lo = ((kt >> 2) == 1);
    int seg = kt >> 2;
    int kc = (kt & 3) * 64;
    for (int i = threadIdx.x; i < 1024; i += 256) {
        int r = i >> 3, u = i & 7;
        const float* src = A + (size_t)(mt*128 + r)*HSZ + kc + u*8;
        float4 f0 = *(const float4*)src;
        float4 f1 = *(const float4*)(src + 4);
        float f[8] = {f0.x, f0.y, f0.z, f0.w, f1.x, f1.y, f1.z, f1.w};
        union { __nv_bfloat16 h[8]; uint4 u4; } o;
        #pragma unroll
        for (int j = 0; j < 8; j++) {
            __nv_bfloat16 hi = __float2bfloat16(f[j]);
            o.h[j] = lo ? __float2bfloat16(f[j] - __bfloat162float(hi)) : hi;
        }
        *(uint4*)(dst + (size_t)(mt*128 + r)*KP + seg*256 + kc + u*8) = o.u4;
    }
}

// ---------------- fused weight conversion (coalesced, [hi|lo] layout) ---------
__global__ void __launch_bounds__(256) conv_weights(
    const float* __restrict__ Wq, const float* __restrict__ Wk, const float* __restrict__ Wv,
    const float* __restrict__ Wao, const float* __restrict__ Wdv, const float* __restrict__ Wf,
    const float* __restrict__ Wvec, const float* __restrict__ Wtrg, const float* __restrict__ Wsrc,
    const float* __restrict__ Ws, const float* __restrict__ Wo,
    __nv_bfloat16* __restrict__ dq, __nv_bfloat16* __restrict__ dao,
    __nv_bfloat16* __restrict__ ddvfw, __nv_bfloat16* __restrict__ dwv1,
    __nv_bfloat16* __restrict__ dv3ts, __nv_bfloat16* __restrict__ dws,
    __nv_bfloat16* __restrict__ dwo)
{
    int t = blockIdx.x;
    const float* src; __nv_bfloat16* dst; int ldb, colOff, ntn, local;
    if (t < 160) {
        int j = t >> 4; local = t & 15; ntn = 4;
        switch (j) {
            case 0: src = Wq;   dst = dq;                       ldb = 256; colOff = 0;   break;
            case 1: src = Wk;   dst = dq + (size_t)256*KP;      ldb = 256; colOff = 0;   break;
            case 2: src = Wv;   dst = dq + (size_t)512*KP;      ldb = 256; colOff = 0;   break;
            case 3: src = Wao;  dst = dao;                      ldb = 256; colOff = 0;   break;
            case 4: src = Wdv;  dst = ddvfw;                    ldb = 256; colOff = 0;   break;
            case 5: src = Wf;   dst = ddvfw + (size_t)256*KP;   ldb = 256; colOff = 0;   break;
            case 6: src = Wvec; dst = dwv1;                     ldb = 512; colOff = 0;   break;
            case 7: src = Wvec; dst = dv3ts;                    ldb = 512; colOff = 256; break;
            case 8: src = Wtrg; dst = dv3ts + (size_t)256*KP;   ldb = 256; colOff = 0;   break;
            default:src = Wsrc; dst = dv3ts + (size_t)512*KP;   ldb = 256; colOff = 0;   break;
        }
    } else if (t < 192) {
        local = t - 160; ntn = 8;
        src = Ws; dst = dws; ldb = 512; colOff = 0;
    } else {
        local = t - 192; ntn = 12;
        src = Wo; dst = dwo; ldb = 768; colOff = 0;
    }
    int nt = local % ntn;
    int kt = local / ntn;
    int base_k = kt * 64;
    int base_n = colOff + nt * 64;

    __shared__ float Wt[64][65];
    int tid = threadIdx.x;
    for (int i = tid; i < 4096; i += 256) {
        int r = i >> 6, c = i & 63;
        Wt[r][c] = src[(size_t)(base_k + r)*ldb + base_n + c];
    }
    __syncthreads();
    for (int i = tid; i < 2048; i += 256) {
        int c = i >> 5;
        int k2 = (i & 31) * 2;
        float v0 = Wt[k2][c], v1 = Wt[k2+1][c];
        __nv_bfloat16 h0 = __float2bfloat16(v0), h1 = __float2bfloat16(v1);
        __nv_bfloat16 l0 = __float2bfloat16(v0 - __bfloat162float(h0));
        __nv_bfloat16 l1 = __float2bfloat16(v1 - __bfloat162float(h1));
        union { __nv_bfloat16 h[2]; uint32_t u; } hp, lp;
        hp.h[0] = h0; hp.h[1] = h1; lp.h[0] = l0; lp.h[1] = l1;
        size_t ro = (size_t)(nt*64 + c)*KP + kt*64 + k2;
        *(uint32_t*)&dst[ro]       = hp.u;   // hi at cols [0,256)
        *(uint32_t*)&dst[ro + 256] = lp.u;   // lo at cols [256,512)
    }
}

// ---------------- mma.sync bf16x3 GEMM core (BK=64, dedup operands) ----------
#define SPITCH 144
#define STILE (128*SPITCH)
#define SSTAGE (2*STILE)
#define GEMM_SMEM (2*SSTAGE)

__device__ __forceinline__ uint32_t smem_u32(const void* p) {
    uint32_t a;
    asm("{ .reg .u64 t; cvta.to.shared.u64 t, %1; cvt.u32.u64 %0, t; }" : "=r"(a) : "l"(p));
    return a;
}

__device__ __forceinline__ void gemm_body(
    const __nv_bfloat16* __restrict__ Aop, const __nv_bfloat16* __restrict__ Bop,
    float* __restrict__ C, int ldc, const float* __restrict__ bias, int act,
    int nt, int mt)
{
    extern __shared__ __align__(16) char smem[];
    int tid = threadIdx.x;
    int lane = tid & 31, wid = tid >> 5;
    int wm = wid & 3, wn = wid >> 2;
    const char* gA = (const char*)Aop + (size_t)mt*128*KP_BYTES;
    const char* gB = (const char*)Bop + (size_t)nt*128*KP_BYTES;
    uint32_t sbase = smem_u32(smem);

    // logical chunk s (0..11): A uses [hi0-3 | lo0-3 | hi0-3], B uses [hi0-3 | hi0-3 | lo0-3]
    auto load_stage = [&](int buf, int s) {
        int sA = (s < 8) ? s : s - 8;      // 0-3 hi, 4-7 lo, then hi again
        int sB = (s < 4) ? s : s - 4;      // 0-3 hi, hi again, 4-7 lo
        uint32_t dst0 = sbase + buf*SSTAGE;
        #pragma unroll
        for (int t = 0; t < 8; t++) {
            int ci = tid + t*256;
            int isB = ci >> 10;
            int cc = ci & 1023;
            int row = cc >> 3, c = cc & 7;
            uint32_t dst = dst0 + isB*STILE + row*SPITCH + c*16;
            const char* src = isB ? gB + (size_t)row*KP_BYTES + sB*128 + c*16
                                  : gA + (size_t)row*KP_BYTES + sA*128 + c*16;
            asm volatile("cp.async.cg.shared.global [%0], [%1], 16;\n" :: "r"(dst), "l"(src));
        }
        asm volatile("cp.async.commit_group;\n");
    };

    float acc[2][8][4];
    #pragma unroll
    for (int i = 0; i < 2; i++)
        #pragma unroll
        for (int j = 0; j < 8; j++)
            #pragma unroll
            for (int k = 0; k < 4; k++) acc[i][j][k] = 0.0f;

    load_stage(0, 0);
    for (int s = 0; s < NSCH; s++) {
        int buf = s & 1;
        if (s + 1 < NSCH) {
            load_stage(buf ^ 1, s + 1);
            asm volatile("cp.async.wait_group 1;\n");
        } else {
            asm volatile("cp.async.wait_group 0;\n");
        }
        __syncthreads();
        uint32_t bA = sbase + buf*SSTAGE;
        uint32_t bB = bA + STILE;
        #pragma unroll
        for (int kk = 0; kk < 64; kk += 16) {
            uint32_t a[2][4];
            #pragma unroll
            for (int mb = 0; mb < 2; mb++) {
                uint32_t addr = bA + (wm*32 + mb*16 + (lane & 15))*SPITCH
                                   + (kk + ((lane >> 4) << 3))*2;
                asm volatile("ldmatrix.sync.aligned.m8n8.x4.shared.b16 {%0,%1,%2,%3}, [%4];"
                    : "=r"(a[mb][0]), "=r"(a[mb][1]), "=r"(a[mb][2]), "=r"(a[mb][3]) : "r"(addr));
            }
            uint32_t b[8][2];
            #pragma unroll
            for (int nb4 = 0; nb4 < 4; nb4++) {
                uint32_t r0, r1, r2, r3;
                uint32_t addr = bB + (wn*64 + nb4*16 + (lane & 15))*SPITCH
                                   + (kk + ((lane >> 4) << 3))*2;
                asm volatile("ldmatrix.sync.aligned.m8n8.x4.shared.b16 {%0,%1,%2,%3}, [%4];"
                    : "=r"(r0), "=r"(r1), "=r"(r2), "=r"(r3) : "r"(addr));
                b[nb4*2][0] = r0; b[nb4*2][1] = r2;
                b[nb4*2+1][0] = r1; b[nb4*2+1][1] = r3;
            }
            #pragma unroll
            for (int mb = 0; mb < 2; mb++)
                #pragma unroll
                for (int nb = 0; nb < 8; nb++)
                    asm volatile("mma.sync.aligned.m16n8k16.row.col.f32.bf16.bf16.f32 "
                        "{%0,%1,%2,%3}, {%4,%5,%6,%7}, {%8,%9}, {%0,%1,%2,%3};"
                        : "+f"(acc[mb][nb][0]), "+f"(acc[mb][nb][1]),
                          "+f"(acc[mb][nb][2]), "+f"(acc[mb][nb][3])
                        : "r"(a[mb][0]), "r"(a[mb][1]), "r"(a[mb][2]), "r"(a[mb][3]),
                          "r"(b[nb][0]), "r"(b[nb][1]));
        }
        __syncthreads();
    }

    int rbase = mt*128 + wm*32 + (lane >> 2);
    int cbase = nt*128 + wn*64 + (lane & 3)*2;
    #pragma unroll
    for (int mb = 0; mb < 2; mb++) {
        #pragma unroll
        for (int nb = 0; nb < 8; nb++) {
            int col = cbase + nb*8;
            float bv0 = 0.0f, bv1 = 0.0f;
            if (bias) { bv0 = bias[col]; bv1 = bias[col+1]; }
            float v0 = acc[mb][nb][0] + bv0, v1 = acc[mb][nb][1] + bv1;
            float v2 = acc[mb][nb][2] + bv0, v3 = acc[mb][nb][3] + bv1;
            if (act) { v0 = silu_f(v0); v1 = silu_f(v1); v2 = silu_f(v2); v3 = silu_f(v3); }
            int r0 = rbase + mb*16;
            *(float2*)&C[(size_t)r0*ldc + col]     = make_float2(v0, v1);
            *(float2*)&C[(size_t)(r0+8)*ldc + col] = make_float2(v2, v3);
        }
    }
}

__global__ void __launch_bounds__(256, 2) gemm_mma(
    const __nv_bfloat16* __restrict__ Aop, const __nv_bfloat16* __restrict__ Bop,
    float* __restrict__ C, int ldc, const float* __restrict__ bias, int act)
{
    gemm_body(Aop, Bop, C, ldc, bias, act, blockIdx.x, blockIdx.y);
}

// ---------------- multi-job GEMM -----------------------------------------------
struct GemmJobs {
    const __nv_bfloat16* A[4];
    const __nv_bfloat16* B[4];
    float* C[4];
    const float* bias[4];
    int ldc[4];
    int act[4];
    int ntiles[4];
    int base[4];
};

__global__ void __launch_bounds__(256, 2) gemm_mma_multi(GemmJobs jobs) {
    int bid = blockIdx.x;
    int ji = 0;
    #pragma unroll
    for (int j = 1; j < 4; j++) if (bid >= jobs.base[j]) ji = j;
    int local = bid - jobs.base[ji];
    int nt = local % jobs.ntiles[ji];
    int mt = local / jobs.ntiles[ji];
    gemm_body(jobs.A[ji], jobs.B[ji], jobs.C[ji], jobs.ldc[ji], jobs.bias[ji],
              jobs.act[ji], nt, mt);
}

// ---------------- LayerNorm (fused [hi|lo] operand write) ---------------------
__global__ void ln_kernel(const float* __restrict__ x,
                          const float* __restrict__ w,
                          const float* __restrict__ b) {
    int n = blockIdx.x;
    int t = threadIdx.x;
    float v = x[n*HSZ + t];
    __shared__ float red[256];
    red[t] = v; __syncthreads();
    for (int s = 128; s > 0; s >>= 1) { if (t < s) red[t] += red[t+s]; __syncthreads(); }
    float mu = red[0] * (1.0f/HSZ);
    __syncthreads();
    float d = v - mu;
    red[t] = d*d; __syncthreads();
    for (int s = 128; s > 0; s >>= 1) { if (t < s) red[t] += red[t+s]; __syncthreads(); }
    float var = red[0] * (1.0f/HSZ);
    float xn = d * rsqrtf(var + 1e-5f) * w[t] + b[t];
    __nv_bfloat16 hi = __float2bfloat16(xn);
    __nv_bfloat16 lo = __float2bfloat16(xn - __bfloat162float(hi));
    __nv_bfloat16* dst = opA_xn + (size_t)n*KP + t;
    dst[0]   = hi;
    dst[256] = lo;
}

// ---------------- fused attention (writes [hi|lo] operand for Wao GEMM) -------
__global__ void __launch_bounds__(256) attn_fused() {
    int b = blockIdx.z, h = blockIdx.y, i0 = blockIdx.x * 32;
    __shared__ float Qs[32][33], Ks[32][33], Vs[32][33], Ss[32][33];
    int tid = threadIdx.x;
    int ti = tid & 31;
    int g  = tid >> 5;

    for (int i = tid; i < 1024; i += 256) {
        int r = i >> 5, c = i & 31;
        Qs[r][c] = g_qkv[(size_t)(b*NSZ + i0 + r)*768 + h*HDSZ + c];
    }
    float acc[4] = {0.0f, 0.0f, 0.0f, 0.0f};

    for (int j0 = 0; j0 < NSZ; j0 += 32) {
        __syncthreads();
        for (int i = tid; i < 1024; i += 256) {
            int r = i >> 5, c = i & 31;
            const float* base = &g_qkv[(size_t)(b*NSZ + j0 + r)*768 + h*HDSZ + c];
            Ks[r][c] = base[256];
            Vs[r][c] = base[512];
        }
        __syncthreads();
        #pragma unroll
        for (int jj = 0; jj < 4; jj++) {
            int j = g*4 + jj;
            float s = 0.0f;
            #pragma unroll
            for (int c = 0; c < HDSZ; c++) s += Qs[ti][c] * Ks[j][c];
            Ss[ti][j] = silu_f(s * 0.1767766952966369f);
        }
        __syncthreads();
        #pragma unroll 8
        for (int j = 0; j < 32; j++) {
            float sv = Ss[ti][j];
            #pragma unroll
            for (int dd = 0; dd < 4; dd++) acc[dd] += sv * Vs[j][g*4 + dd];
        }
    }
    union { __nv_bfloat16 h[2]; uint32_t u; } hp0, hp1, lp0, lp1;
    #pragma unroll
    for (int dd = 0; dd < 4; dd++) {
        float v = acc[dd] * (1.0f/NSZ);
        __nv_bfloat16 hi = __float2bfloat16(v);
        __nv_bfloat16 lo = __float2bfloat16(v - __bfloat162float(hi));
        if (dd < 2) { hp0.h[dd] = hi; lp0.h[dd] = lo; }
        else        { hp1.h[dd-2] = hi; lp1.h[dd-2] = lo; }
    }
    size_t ro = (size_t)(b*NSZ + i0 + ti)*KP + h*HDSZ + g*4;
    *(uint32_t*)&opA_vatt[ro]           = hp0.u;
    *(uint32_t*)&opA_vatt[ro + 2]       = hp1.u;
    *(uint32_t*)&opA_vatt[ro + 256]     = lp0.u;
    *(uint32_t*)&opA_vatt[ro + 258]     = lp1.u;
}

// ---------------- edge-wise / elementwise -------------------------------------
__global__ void concat_bias_kernel(const float* __restrict__ a, const float* __restrict__ b) {
    int i = blockIdx.x*256 + threadIdx.x;
    if (i < 256) g_b_dvfw[i] = a[i];
    else if (i < 512) g_b_dvfw[i] = b[i - 256];
}

// fused: cutoff + v_j compute -> [hi|lo] operand; seg0 also does x_agg atomics
__global__ void vjconv_kernel(const int* __restrict__ ei, const float* __restrict__ r_ij) {
    int kt = blockIdx.x, et = blockIdx.y;     // kt 0..7
    int seg = kt >> 2;
    bool lo = (seg == 1);
    int kc = (kt & 3) * 64;
    for (int i = threadIdx.x; i < 1024; i += 256) {
        int r = i >> 3, u = i & 7;
        int e = et*128 + r;
        int s = ei[e];
        float rr = r_ij[e];
        float cv = (rr < 5.0f) ? 0.5f * (cosf(3.14159265358979323846f * rr / 5.0f) + 1.0f) : 0.0f;
        const float* vp = &g_vao[(size_t)s*HSZ + kc + u*8];
        const float* dp = &g_dvfw[(size_t)e*512 + kc + u*8];
        float4 a0 = *(const float4*)vp,       a1 = *(const float4*)(vp + 4);
        float4 b0 = *(const float4*)dp,       b1 = *(const float4*)(dp + 4);
        float f[8] = {a0.x*cv*b0.x, a0.y*cv*b0.y, a0.z*cv*b0.z, a0.w*cv*b0.w,
                      a1.x*cv*b1.x, a1.y*cv*b1.y, a1.z*cv*b1.z, a1.w*cv*b1.w};
        union { __nv_bfloat16 h[8]; uint4 u4; } o;
        #pragma unroll
        for (int j = 0; j < 8; j++) {
            __nv_bfloat16 hi = __float2bfloat16(f[j]);
            o.h[j] = lo ? __float2bfloat16(f[j] - __bfloat162float(hi)) : hi;
        }
        *(uint4*)(opA_vj + (size_t)e*KP + seg*256 + kc + u*8) = o.u4;
        if (seg == 0) {
            int t2 = ei[ESZ + e];
            float* xa = &g_xagg[(size_t)t2*HSZ + kc + u*8];
            #pragma unroll
            for (int j = 0; j < 8; j++) atomicAdd(xa + j, f[j]);
        }
    }
}

__global__ void scatter_vec_kernel(const int* __restrict__ ei,
                                   const float* __restrict__ vecin,
                                   const float* __restrict__ dij,
                                   float* __restrict__ dvec_out) {
    int e = blockIdx.x;
    int h = threadIdx.x;
    int s = ei[e];
    int t = ei[ESZ + e];
    float s1 = g_s12[(size_t)e*512 + h];
    float s2 = g_s12[(size_t)e*512 + 256 + h];
    #pragma unroll
    for (int d = 0; d < VDSZ; d++) {
        float val = vecin[(size_t)(s*VDSZ + d)*HSZ + h] * s1 + s2 * dij[e*VDSZ + d];
        atomicAdd(&dvec_out[(size_t)(t*VDSZ + d)*HSZ + h], val);
    }
}

__global__ void vecsum_kernel(const float* __restrict__ vecin) {
    int idx = blockIdx.x*256 + threadIdx.x;
    int n = idx >> 8, h = idx & 255;
    float a = 0.0f;
    #pragma unroll
    for (int d = 0; d < VDSZ; d++) a += vecin[(size_t)(n*VDSZ + d)*HSZ + h];
    __nv_bfloat16 hi = __float2bfloat16(a);
    __nv_bfloat16 lo = __float2bfloat16(a - __bfloat162float(hi));
    __nv_bfloat16* dst = opA_vsVD + (size_t)n*KP + h;
    dst[0]   = hi;
    dst[256] = lo;
}

// merged finals: dvec_final part + dx part
__global__ void finals_kernel(float* __restrict__ out_dx, float* __restrict__ dvec_out) {
    int idx = blockIdx.x*256 + threadIdx.x;
    if (idx < BNN*VDSZ*HSZ) {
        int n = idx >> 11;
        int h = idx & 255;
        dvec_out[idx] += g_v3ts[(size_t)((idx >> 8))*768 + h - (size_t)0] * 0.0f
                       + g_v3ts[(size_t)(n*VDSZ + ((idx >> 8) & 7))*768 + h] * g_o[(size_t)n*768 + h];
    } else {
        int k = idx - BNN*VDSZ*HSZ;
        int n = k >> 8, h = k & 255;
        out_dx[k] = g_vecsum[k] * g_o[(size_t)n*768 + 256 + h] + g_o[(size_t)n*768 + 512 + h];
    }
}

__global__ void wdot_kernel(const int* __restrict__ ei,
                            const float* __restrict__ dij,
                            float* __restrict__ df_out) {
    int e = blockIdx.x;
    int h = threadIdx.x;
    int s = ei[e];
    int t = ei[ESZ + e];
    float p1 = 0.0f, p2 = 0.0f, ab = 0.0f, s2n = 0.0f;
    #pragma unroll
    for (int d = 0; d < VDSZ; d++) {
        float dd = dij[e*VDSZ + d];
        float a = g_v3ts[(size_t)(t*VDSZ + d)*768 + 256 + h];
        float b = g_v3ts[(size_t)(s*VDSZ + d)*768 + 512 + h];
        ab  += a*b;
        p1  += a*dd;
        p2  += b*dd;
        s2n += dd*dd;
    }
    float wdot = ab - p1*p2*(2.0f - s2n);
    df_out[(size_t)e*HSZ + h] = g_dvfw[(size_t)e*512 + 256 + h] * wdot;
}

// ---------------- host launcher ----------------------------------------------
extern "C" void kernel_launch(void* const* d_in, const int* in_sizes, int n_in,
                              void* d_out, int out_size) {
    const float* x    = (const float*)d_in[0];
    const float* vec  = (const float*)d_in[1];
    const int*   ei   = (const int*)  d_in[2];
    const float* r_ij = (const float*)d_in[3];
    const float* f_ij = (const float*)d_in[4];
    const float* d_ij = (const float*)d_in[5];
    const float* ln_w = (const float*)d_in[7];
    const float* ln_b = (const float*)d_in[8];
    const float* Wq   = (const float*)d_in[9];
    const float* Wk   = (const float*)d_in[10];
    const float* Wv   = (const float*)d_in[11];
    const float* Wao  = (const float*)d_in[12];
    const float* Wvec = (const float*)d_in[13];
    const float* Wdv  = (const float*)d_in[14];
    const float* bdv  = (const float*)d_in[15];
    const float* Ws   = (const float*)d_in[16];
    const float* bs   = (const float*)d_in[17];
    const float* Wo   = (const float*)d_in[18];
    const float* bo   = (const float*)d_in[19];
    const float* Wf   = (const float*)d_in[20];
    const float* bf   = (const float*)d_in[21];
    const float* Wsrc = (const float*)d_in[22];
    const float* Wtrg = (const float*)d_in[23];

    float* out      = (float*)d_out;
    float* out_dx   = out;
    float* out_dvec = out + BNN*HSZ;
    float* out_df   = out + BNN*HSZ + BNN*VDSZ*HSZ;

    float *p_qkv, *p_vao, *p_dvfw, *p_vsum, *p_v3ts, *p_s12, *p_xagg, *p_o, *p_bdvfw;
    cudaGetSymbolAddress((void**)&p_qkv,  g_qkv);
    cudaGetSymbolAddress((void**)&p_vao,  g_vao);
    cudaGetSymbolAddress((void**)&p_dvfw, g_dvfw);
    cudaGetSymbolAddress((void**)&p_vsum, g_vecsum);
    cudaGetSymbolAddress((void**)&p_v3ts, g_v3ts);
    cudaGetSymbolAddress((void**)&p_s12,  g_s12);
    cudaGetSymbolAddress((void**)&p_xagg, g_xagg);
    cudaGetSymbolAddress((void**)&p_o,    g_o);
    cudaGetSymbolAddress((void**)&p_bdvfw, g_b_dvfw);

    __nv_bfloat16 *pA_xn, *pA_vatt, *pA_vsVD, *pA_xagg, *pA_fij, *pA_vec, *pA_vj;
    __nv_bfloat16 *pB_qkv, *pB_Wao, *pB_dvfw, *pB_Wv1, *pB_v3ts, *pB_Ws, *pB_Wo;
    cudaGetSymbolAddress((void**)&pA_xn,   opA_xn);
    cudaGetSymbolAddress((void**)&pA_vatt, opA_vatt);
    cudaGetSymbolAddress((void**)&pA_vsVD, opA_vsVD);
    cudaGetSymbolAddress((void**)&pA_xagg, opA_xagg);
    cudaGetSymbolAddress((void**)&pA_fij,  opA_fij);
    cudaGetSymbolAddress((void**)&pA_vec,  opA_vec);
    cudaGetSymbolAddress((void**)&pA_vj,   opA_vj);
    cudaGetSymbolAddress((void**)&pB_qkv,  opB_qkv);
    cudaGetSymbolAddress((void**)&pB_Wao,  opB_Wao);
    cudaGetSymbolAddress((void**)&pB_dvfw, opB_dvfw);
    cudaGetSymbolAddress((void**)&pB_Wv1,  opB_Wv1);
    cudaGetSymbolAddress((void**)&pB_v3ts, opB_v3ts);
    cudaGetSymbolAddress((void**)&pB_Ws,   opB_Ws);
    cudaGetSymbolAddress((void**)&pB_Wo,   opB_Wo);

    cudaFuncSetAttribute(gemm_mma, cudaFuncAttributeMaxDynamicSharedMemorySize, GEMM_SMEM);
    cudaFuncSetAttribute(gemm_mma_multi, cudaFuncAttributeMaxDynamicSharedMemorySize, GEMM_SMEM);

    // ---- early memsets ----
    cudaMemsetAsync(p_xagg, 0, (size_t)BNN*HSZ*sizeof(float));
    cudaMemsetAsync(out_dvec, 0, (size_t)BNN*VDSZ*HSZ*sizeof(float));

    // ---- independent producer glue ----
    conv_weights<<<240, 256>>>(Wq, Wk, Wv, Wao, Wdv, Wf, Wvec, Wtrg, Wsrc, Ws, Wo,
                               pB_qkv, pB_Wao, pB_dvfw, pB_Wv1, pB_v3ts, pB_Ws, pB_Wo);
    concat_bias_kernel<<<2,256>>>(bdv, bf);
    ln_kernel<<<BNN,256>>>(x, ln_w, ln_b);
    convA_kernel<<<dim3(8,128),256>>>(f_ij, pA_fij);
    vecsum_kernel<<<BNN*HSZ/256,256>>>(vec);
    convA_kernel<<<dim3(8,128),256>>>(vec, pA_vec);

    // ---- mega-GEMM 1: v3ts + dvfw + qkv + Wv1 ----
    {
        GemmJobs jobs;
        jobs.A[0] = pA_vec;  jobs.B[0] = pB_v3ts; jobs.C[0] = p_v3ts; jobs.bias[0] = nullptr;
        jobs.ldc[0] = 768;   jobs.act[0] = 0;     jobs.ntiles[0] = 6; jobs.base[0] = 0;
        jobs.A[1] = pA_fij;  jobs.B[1] = pB_dvfw; jobs.C[1] = p_dvfw; jobs.bias[1] = p_bdvfw;
        jobs.ldc[1] = 512;   jobs.act[1] = 1;     jobs.ntiles[1] = 4; jobs.base[1] = 768;
        jobs.A[2] = pA_xn;   jobs.B[2] = pB_qkv;  jobs.C[2] = p_qkv;  jobs.bias[2] = nullptr;
        jobs.ldc[2] = 768;   jobs.act[2] = 0;     jobs.ntiles[2] = 6; jobs.base[2] = 1280;
        jobs.A[3] = pA_vsVD; jobs.B[3] = pB_Wv1;  jobs.C[3] = p_vsum; jobs.bias[3] = nullptr;
        jobs.ldc[3] = 256;   jobs.act[3] = 0;     jobs.ntiles[3] = 2; jobs.base[3] = 1376;
        gemm_mma_multi<<<1408, 256, GEMM_SMEM>>>(jobs);
    }

    // ---- attention + Wao GEMM (per-head attention; Wao stays separate) ----
    attn_fused<<<dim3(NSZ/32, NHSZ, BSZ),256>>>();
    gemm_mma<<<dim3(2,16),256,GEMM_SMEM>>>(pA_vatt, pB_Wao, p_vao, 256, nullptr, 0);

    // ---- edge tail: vjconv (+x_agg atomics) -> convA_xagg -> {Ws, Wo} batch ----
    vjconv_kernel<<<dim3(8,128),256>>>(ei, r_ij);
    convA_kernel<<<dim3(8,16),256>>>(p_xagg, pA_xagg);
    {
        GemmJobs jobs;
        jobs.A[0] = pA_vj;   jobs.B[0] = pB_Ws; jobs.C[0] = p_s12; jobs.bias[0] = bs;
        jobs.ldc[0] = 512;   jobs.act[0] = 1;   jobs.ntiles[0] = 4; jobs.base[0] = 0;
        jobs.A[1] = pA_xagg; jobs.B[1] = pB_Wo; jobs.C[1] = p_o;   jobs.bias[1] = bo;
        jobs.ldc[1] = 768;   jobs.act[1] = 0;   jobs.ntiles[1] = 6; jobs.base[1] = 512;
        jobs.A[2] = jobs.A[0]; jobs.B[2] = jobs.B[0]; jobs.C[2] = jobs.C[0]; jobs.bias[2] = nullptr;
        jobs.ldc[2] = 512; jobs.act[2] = 0; jobs.ntiles[2] = 1; jobs.base[2] = 1 << 30;
        jobs.A[3] = jobs.A[0]; jobs.B[3] = jobs.B[0]; jobs.C[3] = jobs.C[0]; jobs.bias[3] = nullptr;
        jobs.ldc[3] = 512; jobs.act[3] = 0; jobs.ntiles[3] = 1; jobs.base[3] = 1 << 30;
        gemm_mma_multi<<<608, 256, GEMM_SMEM>>>(jobs);
    }

    // ---- finals ----
    scatter_vec_kernel<<<ESZ,256>>>(ei, vec, d_ij, out_dvec);
    wdot_kernel<<<ESZ,256>>>(ei, d_ij, out_df);
    finals_kernel<<<(BNN*VDSZ*HSZ + BNN*HSZ)/256,256>>>(out_dx, out_dvec);
}